// round 2
// baseline (speedup 1.0000x reference)
#include <cuda_runtime.h>

#define N_POL   100000
#define N_TICK  20000
#define NN      (N_POL + N_TICK)   // 120000
#define E_EDGES 1000000
#define POL_FEAT 7
#define EMB     128
#define HID     256
#define OUTD    128

// ---------------- scratch (static device globals; no allocation) ----------------
__device__ float g_x[(size_t)NN * EMB];     // node features        61.4 MB
__device__ float g_agg1[(size_t)NN * EMB];  // layer-1 aggregation  61.4 MB
__device__ float g_h[(size_t)NN * HID];     // hidden              122.9 MB
__device__ float g_y[(size_t)NN * EMB];     // h @ W2_rel           61.4 MB

// ---------------- kernel 1: build x = [relu(pol@Wp+b)+state_emb | tick], zero agg1 ----------------
__global__ __launch_bounds__(256)
void build_x_kernel(const float* __restrict__ pol, const int* __restrict__ sid,
                    const float* __restrict__ Wp, const float* __restrict__ bp,
                    const float* __restrict__ semb, const float* __restrict__ tick)
{
    int t = blockIdx.x * blockDim.x + threadIdx.x;      // one thread = 4 emb dims of one node
    int node = t >> 5;                                  // 32 chunks of 4 per node
    int c4 = (t & 31) * 4;
    if (node >= NN) return;

    // fused zeroing of agg1 (same index space)
    *(float4*)(g_agg1 + (size_t)node * EMB + c4) = make_float4(0.f, 0.f, 0.f, 0.f);

    float4 r;
    if (node < N_POL) {
        float4 acc = *(const float4*)(bp + c4);
        #pragma unroll
        for (int k = 0; k < POL_FEAT; k++) {
            float f = __ldg(pol + node * POL_FEAT + k);
            float4 w = *(const float4*)(Wp + k * EMB + c4);
            acc.x += f * w.x; acc.y += f * w.y; acc.z += f * w.z; acc.w += f * w.w;
        }
        int s = sid[node];
        float4 se = *(const float4*)(semb + (size_t)s * EMB + c4);
        r.x = fmaxf(acc.x, 0.f) + se.x;
        r.y = fmaxf(acc.y, 0.f) + se.y;
        r.z = fmaxf(acc.z, 0.f) + se.z;
        r.w = fmaxf(acc.w, 0.f) + se.w;
    } else {
        r = *(const float4*)(tick + (size_t)(node - N_POL) * EMB + c4);
    }
    *(float4*)(g_x + (size_t)node * EMB + c4) = r;
}

// ---------------- scatter: dst[d] += w * src[s], 128 dims, one warp per edge ----------------
// LAYER=1: src = g_x,  dst = g_agg1 (device globals referenced in device code)
// LAYER=2: src = g_y,  dst = ext (d_out)
template <int LAYER>
__global__ __launch_bounds__(256)
void scatter_kernel(const int* __restrict__ ei, const float* __restrict__ ew,
                    float* __restrict__ ext)
{
    int t = blockIdx.x * blockDim.x + threadIdx.x;
    int e = t >> 5;
    int c4 = (t & 31) * 4;
    if (e >= E_EDGES) return;

    int s = ei[e];
    int d = ei[E_EDGES + e];
    float w = ew[e];

    const float* src = (LAYER == 1) ? g_x : g_y;
    float*       dst = (LAYER == 1) ? g_agg1 : ext;

    float4 v = *(const float4*)(src + (size_t)s * EMB + c4);
    float* o = dst + (size_t)d * EMB + c4;
    atomicAdd(o + 0, v.x * w);
    atomicAdd(o + 1, v.y * w);
    atomicAdd(o + 2, v.z * w);
    atomicAdd(o + 3, v.w * w);
}

// ---------------- fused GEMMs ----------------
// MODE 1:  h[N,256] = relu( [agg1|x] @ [W1_rel ; W1_root] + b1 )        (virtual K=256)
// MODE 2:  [y | out] = h @ [W2_rel | W2_root],  out += b2               (virtual N=256)
template <int MODE>
__global__ __launch_bounds__(256)
void gcn_gemm_kernel(const float* __restrict__ Brel,
                     const float* __restrict__ Broot,
                     const float* __restrict__ bias,
                     float* __restrict__ dout)
{
    constexpr int BM = 64, BN = 64, BK = 32;
    __shared__ float As[BM][BK];      // [m][k]
    __shared__ float Bs[BK][BN];      // [k][n]

    const int tid = threadIdx.x;
    const int m0 = blockIdx.x * BM;
    const int n0 = blockIdx.y * BN;

    const int ty = tid >> 4;          // 0..15  (4 rows each)
    const int tx = tid & 15;          // 0..15  (4 cols each)

    const int aq = tid & 7, ar = tid >> 3;    // A loader: k-chunk, row
    const int bq = tid & 15, br = tid >> 4;   // B loader: n-chunk, row

    float acc[4][4] = {};

    for (int k0 = 0; k0 < 256; k0 += BK) {
        // ---- A tile
        const float* Asrc; int astr, kb;
        if (MODE == 1) { Asrc = (k0 < 128) ? g_agg1 : g_x; astr = 128; kb = k0 & 127; }
        else           { Asrc = g_h;                       astr = 256; kb = k0; }
        #pragma unroll
        for (int i = 0; i < 2; i++) {
            int r = ar + i * 32;
            float4 v = *(const float4*)(Asrc + (size_t)(m0 + r) * astr + kb + aq * 4);
            *(float4*)&As[r][aq * 4] = v;
        }
        // ---- B tile
        const float* Bsrc; int bstr, nb;
        if (MODE == 1) {
            Bsrc = (k0 < 128) ? (Brel + (size_t)k0 * 256) : (Broot + (size_t)(k0 - 128) * 256);
            bstr = 256; nb = n0;
        } else {
            Bsrc = ((n0 < 128) ? Brel : Broot) + (size_t)k0 * 128;
            bstr = 128; nb = n0 & 127;
        }
        #pragma unroll
        for (int i = 0; i < 2; i++) {
            int r = br + i * 16;
            float4 v = *(const float4*)(Bsrc + (size_t)r * bstr + nb + bq * 4);
            *(float4*)&Bs[r][bq * 4] = v;
        }
        __syncthreads();

        #pragma unroll
        for (int kk = 0; kk < BK; kk++) {
            float a0 = As[ty * 4 + 0][kk];
            float a1 = As[ty * 4 + 1][kk];
            float a2 = As[ty * 4 + 2][kk];
            float a3 = As[ty * 4 + 3][kk];
            float4 b = *(float4*)&Bs[kk][tx * 4];
            acc[0][0] += a0 * b.x; acc[0][1] += a0 * b.y; acc[0][2] += a0 * b.z; acc[0][3] += a0 * b.w;
            acc[1][0] += a1 * b.x; acc[1][1] += a1 * b.y; acc[1][2] += a1 * b.z; acc[1][3] += a1 * b.w;
            acc[2][0] += a2 * b.x; acc[2][1] += a2 * b.y; acc[2][2] += a2 * b.z; acc[2][3] += a2 * b.w;
            acc[3][0] += a3 * b.x; acc[3][1] += a3 * b.y; acc[3][2] += a3 * b.z; acc[3][3] += a3 * b.w;
        }
        __syncthreads();
    }

    // ---- epilogue
    if (MODE == 1) {
        float4 bv = *(const float4*)(bias + n0 + tx * 4);
        #pragma unroll
        for (int i = 0; i < 4; i++) {
            size_t row = (size_t)(m0 + ty * 4 + i);
            float4 o;
            o.x = fmaxf(acc[i][0] + bv.x, 0.f);
            o.y = fmaxf(acc[i][1] + bv.y, 0.f);
            o.z = fmaxf(acc[i][2] + bv.z, 0.f);
            o.w = fmaxf(acc[i][3] + bv.w, 0.f);
            *(float4*)(g_h + row * 256 + n0 + tx * 4) = o;
        }
    } else {
        if (n0 < 128) {
            // y = h @ W2_rel
            #pragma unroll
            for (int i = 0; i < 4; i++) {
                size_t row = (size_t)(m0 + ty * 4 + i);
                float4 o = make_float4(acc[i][0], acc[i][1], acc[i][2], acc[i][3]);
                *(float4*)(g_y + row * 128 + n0 + tx * 4) = o;
            }
        } else {
            // out = h @ W2_root + b2  (scatter of y is atomically added afterward)
            int nc = (n0 - 128) + tx * 4;
            float4 bv = *(const float4*)(bias + nc);
            #pragma unroll
            for (int i = 0; i < 4; i++) {
                size_t row = (size_t)(m0 + ty * 4 + i);
                float4 o;
                o.x = acc[i][0] + bv.x;
                o.y = acc[i][1] + bv.y;
                o.z = acc[i][2] + bv.z;
                o.w = acc[i][3] + bv.w;
                *(float4*)(dout + row * 128 + nc) = o;
            }
        }
    }
}

// ---------------- launch ----------------
extern "C" void kernel_launch(void* const* d_in, const int* in_sizes, int n_in,
                              void* d_out, int out_size)
{
    const float* pol   = (const float*)d_in[0];
    const int*   sid   = (const int*)  d_in[1];
    const int*   ei    = (const int*)  d_in[2];
    const float* ew    = (const float*)d_in[3];
    const float* Wp    = (const float*)d_in[4];
    const float* bp    = (const float*)d_in[5];
    const float* semb  = (const float*)d_in[6];
    const float* tick  = (const float*)d_in[7];
    const float* W1rel = (const float*)d_in[8];
    const float* b1    = (const float*)d_in[9];
    const float* W1root= (const float*)d_in[10];
    const float* W2rel = (const float*)d_in[11];
    const float* b2    = (const float*)d_in[12];
    const float* W2root= (const float*)d_in[13];
    float* out = (float*)d_out;

    // 1) x build + zero agg1
    {
        int threads = NN * 32;
        build_x_kernel<<<(threads + 255) / 256, 256>>>(pol, sid, Wp, bp, semb, tick);
    }
    // 2) scatter layer 1: agg1[dst] += w * x[src]
    {
        long threads = (long)E_EDGES * 32;
        scatter_kernel<1><<<(int)((threads + 255) / 256), 256>>>(ei, ew, nullptr);
    }
    // 3) h = relu([agg1|x] @ [W1_rel;W1_root] + b1)
    {
        dim3 grid(NN / 64, 256 / 64);
        gcn_gemm_kernel<1><<<grid, 256>>>(W1rel, W1root, b1, nullptr);
    }
    // 4) y = h @ W2_rel ; out = h @ W2_root + b2
    {
        dim3 grid(NN / 64, 256 / 64);
        gcn_gemm_kernel<2><<<grid, 256>>>(W2rel, W2root, b2, out);
    }
    // 5) scatter layer 2 directly into out: out[dst] += w * y[src]
    {
        long threads = (long)E_EDGES * 32;
        scatter_kernel<2><<<(int)((threads + 255) / 256), 256>>>(ei, ew, out);
    }
}

// round 3
// speedup vs baseline: 1.3241x; 1.3241x over previous
#include <cuda_runtime.h>

#define N_POL   100000
#define N_TICK  20000
#define NN      (N_POL + N_TICK)   // 120000
#define NPAD    120064             // 938 * 128
#define E_EDGES 1000000
#define POL_FEAT 7
#define EMB     128
#define HID     256
#define OUTD    128

// ---------------- scratch (static device globals; no allocation) ----------------
__device__ float g_x[(size_t)NPAD * EMB];     // node features
__device__ float g_agg1[(size_t)NPAD * EMB];  // layer-1 aggregation
__device__ float g_h[(size_t)NPAD * HID];     // hidden
__device__ float g_y[(size_t)NPAD * EMB];     // h @ W2_rel

// ---------------- packed f32x2 helpers (Blackwell FFMA2 path) ----------------
#define FMA2(c, a, b) asm volatile("fma.rn.f32x2 %0, %1, %2, %0;" : "+l"(c) : "l"(a), "l"(b))
#define DUP2(d, f)    asm volatile("mov.b64 %0, {%1, %1};" : "=l"(d) : "f"(f))

// ---------------- kernel 1: build x = [relu(pol@Wp+b)+state_emb | tick], zero agg1 ----------------
__global__ __launch_bounds__(256)
void build_x_kernel(const float* __restrict__ pol, const int* __restrict__ sid,
                    const float* __restrict__ Wp, const float* __restrict__ bp,
                    const float* __restrict__ semb, const float* __restrict__ tick)
{
    int t = blockIdx.x * blockDim.x + threadIdx.x;      // one thread = 4 emb dims of one node
    int node = t >> 5;                                  // 32 chunks of 4 per node
    int c4 = (t & 31) * 4;
    if (node >= NN) return;

    *(float4*)(g_agg1 + (size_t)node * EMB + c4) = make_float4(0.f, 0.f, 0.f, 0.f);

    float4 r;
    if (node < N_POL) {
        float4 acc = *(const float4*)(bp + c4);
        #pragma unroll
        for (int k = 0; k < POL_FEAT; k++) {
            float f = __ldg(pol + node * POL_FEAT + k);
            float4 w = *(const float4*)(Wp + k * EMB + c4);
            acc.x += f * w.x; acc.y += f * w.y; acc.z += f * w.z; acc.w += f * w.w;
        }
        int s = sid[node];
        float4 se = *(const float4*)(semb + (size_t)s * EMB + c4);
        r.x = fmaxf(acc.x, 0.f) + se.x;
        r.y = fmaxf(acc.y, 0.f) + se.y;
        r.z = fmaxf(acc.z, 0.f) + se.z;
        r.w = fmaxf(acc.w, 0.f) + se.w;
    } else {
        r = *(const float4*)(tick + (size_t)(node - N_POL) * EMB + c4);
    }
    *(float4*)(g_x + (size_t)node * EMB + c4) = r;
}

// ---------------- scatter: dst[d] += w * src[s], 128 dims, one warp per edge ----------------
// LAYER=1: src = g_x,  dst = g_agg1     LAYER=2: src = g_y, dst = ext (d_out)
template <int LAYER>
__global__ __launch_bounds__(256)
void scatter_kernel(const int* __restrict__ ei, const float* __restrict__ ew,
                    float* __restrict__ ext)
{
    int t = blockIdx.x * blockDim.x + threadIdx.x;
    int e = t >> 5;
    int c4 = (t & 31) * 4;
    if (e >= E_EDGES) return;

    int s = ei[e];
    int d = ei[E_EDGES + e];
    float w = ew[e];

    const float* src = (LAYER == 1) ? g_x : g_y;
    float*       dst = (LAYER == 1) ? g_agg1 : ext;

    float4 v = *(const float4*)(src + (size_t)s * EMB + c4);
    float* o = dst + (size_t)d * EMB + c4;
    // vector f32 reduction (sm_90+): one instruction for 4 adds
    asm volatile("red.global.add.v4.f32 [%0], {%1, %2, %3, %4};"
                 :: "l"(o), "f"(v.x * w), "f"(v.y * w), "f"(v.z * w), "f"(v.w * w)
                 : "memory");
}

// ---------------- fused GEMMs (packed f32x2, BM=BN=128, BK=16, 8x8/thread) ----------------
// MODE 1:  h[N,256] = relu( [agg1|x] @ [W1_rel ; W1_root] + b1 )        (virtual K=256)
// MODE 2:  [y | out] = h @ [W2_rel | W2_root],  out += b2               (virtual N=256)
template <int MODE>
__global__ __launch_bounds__(256, 2)
void gcn_gemm_kernel(const float* __restrict__ Brel,
                     const float* __restrict__ Broot,
                     const float* __restrict__ bias,
                     float* __restrict__ dout)
{
    constexpr int BM = 128, BN = 128, BK = 16;
    __shared__ float As[BK][BM];      // k-major: m contiguous
    __shared__ float Bs[BK][BN];      // n contiguous

    const int tid = threadIdx.x;
    const int m0 = blockIdx.x * BM;
    const int n0 = blockIdx.y * BN;

    const int tx = tid & 15;          // n-block: 8 cols
    const int ty = tid >> 4;          // m-block: 8 rows
    const int tm = ty * 8;
    const int tn = tx * 8;

    // A loader: consecutive threads cover k (coalesced); 4 k-quads x 64 rows
    const int aq = tid & 3;           // k-quad -> k = aq*4
    const int ar = tid >> 2;          // row 0..63 (+64)
    // B loader: 32 n-quads x 8 rows (+8)
    const int bq = tid & 31;
    const int br = tid >> 5;

    unsigned long long acc2[4][8];    // [m-pair][n], 64 fp32 accumulators
    #pragma unroll
    for (int i = 0; i < 4; i++)
        #pragma unroll
        for (int j = 0; j < 8; j++) acc2[i][j] = 0ull;

    for (int k0 = 0; k0 < 256; k0 += BK) {
        // ---- A tile (global row-major -> smem k-major)
        const float* Asrc; int astr, kb;
        if (MODE == 1) { Asrc = (k0 < 128) ? g_agg1 : g_x; astr = 128; kb = k0 & 127; }
        else           { Asrc = g_h;                       astr = 256; kb = k0; }
        #pragma unroll
        for (int i = 0; i < 2; i++) {
            int r = ar + i * 64;
            float4 v = *(const float4*)(Asrc + (size_t)(m0 + r) * astr + kb + aq * 4);
            As[aq * 4 + 0][r] = v.x;
            As[aq * 4 + 1][r] = v.y;
            As[aq * 4 + 2][r] = v.z;
            As[aq * 4 + 3][r] = v.w;
        }
        // ---- B tile
        const float* Bsrc; int bstr, nb;
        if (MODE == 1) {
            Bsrc = (k0 < 128) ? (Brel + (size_t)k0 * 256) : (Broot + (size_t)(k0 - 128) * 256);
            bstr = 256; nb = n0;
        } else {
            Bsrc = ((n0 < 128) ? Brel : Broot) + (size_t)k0 * 128;
            bstr = 128; nb = n0 & 127;
        }
        #pragma unroll
        for (int i = 0; i < 2; i++) {
            int r = br + i * 8;
            float4 v = *(const float4*)(Bsrc + (size_t)r * bstr + nb + bq * 4);
            *(float4*)&Bs[r][bq * 4] = v;
        }
        __syncthreads();

        #pragma unroll
        for (int kk = 0; kk < BK; kk++) {
            // 8 m-values, already paired as f32x2 (m contiguous in smem)
            ulonglong2 a01 = *(const ulonglong2*)&As[kk][tm];
            ulonglong2 a23 = *(const ulonglong2*)&As[kk][tm + 4];
            float4 b0 = *(const float4*)&Bs[kk][tn];
            float4 b1 = *(const float4*)&Bs[kk][tn + 4];
            unsigned long long db[8];
            DUP2(db[0], b0.x); DUP2(db[1], b0.y); DUP2(db[2], b0.z); DUP2(db[3], b0.w);
            DUP2(db[4], b1.x); DUP2(db[5], b1.y); DUP2(db[6], b1.z); DUP2(db[7], b1.w);
            #pragma unroll
            for (int j = 0; j < 8; j++) {
                FMA2(acc2[0][j], a01.x, db[j]);
                FMA2(acc2[1][j], a01.y, db[j]);
                FMA2(acc2[2][j], a23.x, db[j]);
                FMA2(acc2[3][j], a23.y, db[j]);
            }
        }
        __syncthreads();
    }

    // unpack: acc2[mp][n] -> rows tm+2*mp (lo), tm+2*mp+1 (hi)
    if (MODE == 1) {
        float4 bv0 = *(const float4*)(bias + n0 + tn);
        float4 bv1 = *(const float4*)(bias + n0 + tn + 4);
        #pragma unroll
        for (int mp = 0; mp < 4; mp++) {
            #pragma unroll
            for (int hh = 0; hh < 2; hh++) {
                size_t row = (size_t)(m0 + tm + mp * 2 + hh);
                float4 o0, o1;
                o0.x = fmaxf(((const float2*)&acc2[mp][0])[0].y * 0.f +
                             (hh ? ((const float2*)&acc2[mp][0])->y : ((const float2*)&acc2[mp][0])->x) + bv0.x, 0.f);
                // (expanded explicitly below for clarity/correctness)
                float v0 = hh ? ((const float2*)&acc2[mp][0])->y : ((const float2*)&acc2[mp][0])->x;
                float v1 = hh ? ((const float2*)&acc2[mp][1])->y : ((const float2*)&acc2[mp][1])->x;
                float v2 = hh ? ((const float2*)&acc2[mp][2])->y : ((const float2*)&acc2[mp][2])->x;
                float v3 = hh ? ((const float2*)&acc2[mp][3])->y : ((const float2*)&acc2[mp][3])->x;
                float v4 = hh ? ((const float2*)&acc2[mp][4])->y : ((const float2*)&acc2[mp][4])->x;
                float v5 = hh ? ((const float2*)&acc2[mp][5])->y : ((const float2*)&acc2[mp][5])->x;
                float v6 = hh ? ((const float2*)&acc2[mp][6])->y : ((const float2*)&acc2[mp][6])->x;
                float v7 = hh ? ((const float2*)&acc2[mp][7])->y : ((const float2*)&acc2[mp][7])->x;
                o0.x = fmaxf(v0 + bv0.x, 0.f); o0.y = fmaxf(v1 + bv0.y, 0.f);
                o0.z = fmaxf(v2 + bv0.z, 0.f); o0.w = fmaxf(v3 + bv0.w, 0.f);
                o1.x = fmaxf(v4 + bv1.x, 0.f); o1.y = fmaxf(v5 + bv1.y, 0.f);
                o1.z = fmaxf(v6 + bv1.z, 0.f); o1.w = fmaxf(v7 + bv1.w, 0.f);
                *(float4*)(g_h + row * 256 + n0 + tn)     = o0;
                *(float4*)(g_h + row * 256 + n0 + tn + 4) = o1;
            }
        }
    } else {
        if (n0 < 128) {
            #pragma unroll
            for (int mp = 0; mp < 4; mp++) {
                #pragma unroll
                for (int hh = 0; hh < 2; hh++) {
                    size_t row = (size_t)(m0 + tm + mp * 2 + hh);
                    float4 o0, o1;
                    o0.x = hh ? ((const float2*)&acc2[mp][0])->y : ((const float2*)&acc2[mp][0])->x;
                    o0.y = hh ? ((const float2*)&acc2[mp][1])->y : ((const float2*)&acc2[mp][1])->x;
                    o0.z = hh ? ((const float2*)&acc2[mp][2])->y : ((const float2*)&acc2[mp][2])->x;
                    o0.w = hh ? ((const float2*)&acc2[mp][3])->y : ((const float2*)&acc2[mp][3])->x;
                    o1.x = hh ? ((const float2*)&acc2[mp][4])->y : ((const float2*)&acc2[mp][4])->x;
                    o1.y = hh ? ((const float2*)&acc2[mp][5])->y : ((const float2*)&acc2[mp][5])->x;
                    o1.z = hh ? ((const float2*)&acc2[mp][6])->y : ((const float2*)&acc2[mp][6])->x;
                    o1.w = hh ? ((const float2*)&acc2[mp][7])->y : ((const float2*)&acc2[mp][7])->x;
                    *(float4*)(g_y + row * 128 + tn)     = o0;
                    *(float4*)(g_y + row * 128 + tn + 4) = o1;
                }
            }
        } else {
            float4 bv0 = *(const float4*)(bias + tn);
            float4 bv1 = *(const float4*)(bias + tn + 4);
            #pragma unroll
            for (int mp = 0; mp < 4; mp++) {
                #pragma unroll
                for (int hh = 0; hh < 2; hh++) {
                    int row = m0 + tm + mp * 2 + hh;
                    if (row >= NN) continue;
                    float4 o0, o1;
                    o0.x = (hh ? ((const float2*)&acc2[mp][0])->y : ((const float2*)&acc2[mp][0])->x) + bv0.x;
                    o0.y = (hh ? ((const float2*)&acc2[mp][1])->y : ((const float2*)&acc2[mp][1])->x) + bv0.y;
                    o0.z = (hh ? ((const float2*)&acc2[mp][2])->y : ((const float2*)&acc2[mp][2])->x) + bv0.z;
                    o0.w = (hh ? ((const float2*)&acc2[mp][3])->y : ((const float2*)&acc2[mp][3])->x) + bv0.w;
                    o1.x = (hh ? ((const float2*)&acc2[mp][4])->y : ((const float2*)&acc2[mp][4])->x) + bv1.x;
                    o1.y = (hh ? ((const float2*)&acc2[mp][5])->y : ((const float2*)&acc2[mp][5])->x) + bv1.y;
                    o1.z = (hh ? ((const float2*)&acc2[mp][6])->y : ((const float2*)&acc2[mp][6])->x) + bv1.z;
                    o1.w = (hh ? ((const float2*)&acc2[mp][7])->y : ((const float2*)&acc2[mp][7])->x) + bv1.w;
                    *(float4*)(dout + (size_t)row * 128 + tn)     = o0;
                    *(float4*)(dout + (size_t)row * 128 + tn + 4) = o1;
                }
            }
        }
    }
}

// ---------------- launch ----------------
extern "C" void kernel_launch(void* const* d_in, const int* in_sizes, int n_in,
                              void* d_out, int out_size)
{
    const float* pol   = (const float*)d_in[0];
    const int*   sid   = (const int*)  d_in[1];
    const int*   ei    = (const int*)  d_in[2];
    const float* ew    = (const float*)d_in[3];
    const float* Wp    = (const float*)d_in[4];
    const float* bp    = (const float*)d_in[5];
    const float* semb  = (const float*)d_in[6];
    const float* tick  = (const float*)d_in[7];
    const float* W1rel = (const float*)d_in[8];
    const float* b1    = (const float*)d_in[9];
    const float* W1root= (const float*)d_in[10];
    const float* W2rel = (const float*)d_in[11];
    const float* b2    = (const float*)d_in[12];
    const float* W2root= (const float*)d_in[13];
    float* out = (float*)d_out;

    // 1) x build + zero agg1
    {
        int threads = NN * 32;
        build_x_kernel<<<(threads + 255) / 256, 256>>>(pol, sid, Wp, bp, semb, tick);
    }
    // 2) scatter layer 1: agg1[dst] += w * x[src]
    {
        long threads = (long)E_EDGES * 32;
        scatter_kernel<1><<<(int)((threads + 255) / 256), 256>>>(ei, ew, nullptr);
    }
    // 3) h = relu([agg1|x] @ [W1_rel;W1_root] + b1)
    {
        dim3 grid(NPAD / 128, 2);
        gcn_gemm_kernel<1><<<grid, 256>>>(W1rel, W1root, b1, nullptr);
    }
    // 4) y = h @ W2_rel ; out = h @ W2_root + b2
    {
        dim3 grid(NPAD / 128, 2);
        gcn_gemm_kernel<2><<<grid, 256>>>(W2rel, W2root, b2, out);
    }
    // 5) scatter layer 2 directly into out: out[dst] += w * y[src]
    {
        long threads = (long)E_EDGES * 32;
        scatter_kernel<2><<<(int)((threads + 255) / 256), 256>>>(ei, ew, out);
    }
}

// round 5
// speedup vs baseline: 1.7806x; 1.3448x over previous
#include <cuda_runtime.h>
#include <cuda_bf16.h>
#include <cstdint>

#define N_POL   100000
#define N_TICK  20000
#define NN      (N_POL + N_TICK)   // 120000
#define NPAD    120064             // 938 * 128
#define E_EDGES 1000000
#define POL_FEAT 7
#define EMB     128
#define HID     256
#define OUTD    128

// ---------------- scratch (static device globals; no allocation) ----------------
__device__ float g_x[(size_t)NPAD * EMB];     // node features
__device__ float g_agg1[(size_t)NPAD * EMB];  // layer-1 aggregation
__device__ float g_h[(size_t)NPAD * HID];     // hidden
__device__ float g_y[(size_t)NPAD * EMB];     // h @ W2_rel

// ---------------- helpers ----------------
__device__ __forceinline__ uint32_t smem_u32(const void* p) {
    uint32_t a;
    asm("{ .reg .u64 t; cvta.to.shared.u64 t, %1; cvt.u32.u64 %0, t; }" : "=r"(a) : "l"(p));
    return a;
}

#define LDSM_X4(r0, r1, r2, r3, addr) \
    asm volatile("ldmatrix.sync.aligned.m8n8.x4.shared.b16 {%0,%1,%2,%3}, [%4];" \
        : "=r"(r0), "=r"(r1), "=r"(r2), "=r"(r3) : "r"(addr))

#define MMA_BF16(c, a, b0, b1) \
    asm volatile("mma.sync.aligned.m16n8k16.row.col.f32.bf16.bf16.f32 " \
        "{%0,%1,%2,%3}, {%4,%5,%6,%7}, {%8,%9}, {%0,%1,%2,%3};" \
        : "+f"((c)[0]), "+f"((c)[1]), "+f"((c)[2]), "+f"((c)[3]) \
        : "r"((a)[0]), "r"((a)[1]), "r"((a)[2]), "r"((a)[3]), "r"(b0), "r"(b1))

__device__ __forceinline__ void split1(float v, uint16_t& h, uint16_t& l) {
    __nv_bfloat16 bh = __float2bfloat16(v);
    float fh = __bfloat162float(bh);
    __nv_bfloat16 bl = __float2bfloat16(v - fh);
    h = *reinterpret_cast<uint16_t*>(&bh);
    l = *reinterpret_cast<uint16_t*>(&bl);
}

// ---------------- kernel 1: build x, zero agg1 ----------------
__global__ __launch_bounds__(256)
void build_x_kernel(const float* __restrict__ pol, const int* __restrict__ sid,
                    const float* __restrict__ Wp, const float* __restrict__ bp,
                    const float* __restrict__ semb, const float* __restrict__ tick)
{
    int t = blockIdx.x * blockDim.x + threadIdx.x;
    int node = t >> 5;
    int c4 = (t & 31) * 4;
    if (node >= NN) return;

    *(float4*)(g_agg1 + (size_t)node * EMB + c4) = make_float4(0.f, 0.f, 0.f, 0.f);

    float4 r;
    if (node < N_POL) {
        float4 acc = *(const float4*)(bp + c4);
        #pragma unroll
        for (int k = 0; k < POL_FEAT; k++) {
            float f = __ldg(pol + node * POL_FEAT + k);
            float4 w = *(const float4*)(Wp + k * EMB + c4);
            acc.x += f * w.x; acc.y += f * w.y; acc.z += f * w.z; acc.w += f * w.w;
        }
        int s = sid[node];
        float4 se = *(const float4*)(semb + (size_t)s * EMB + c4);
        r.x = fmaxf(acc.x, 0.f) + se.x;
        r.y = fmaxf(acc.y, 0.f) + se.y;
        r.z = fmaxf(acc.z, 0.f) + se.z;
        r.w = fmaxf(acc.w, 0.f) + se.w;
    } else {
        r = *(const float4*)(tick + (size_t)(node - N_POL) * EMB + c4);
    }
    *(float4*)(g_x + (size_t)node * EMB + c4) = r;
}

// ---------------- scatter: dst[d] += w * src[s], one warp per edge ----------------
template <int LAYER>
__global__ __launch_bounds__(256)
void scatter_kernel(const int* __restrict__ ei, const float* __restrict__ ew,
                    float* __restrict__ ext)
{
    int t = blockIdx.x * blockDim.x + threadIdx.x;
    int e = t >> 5;
    int c4 = (t & 31) * 4;
    if (e >= E_EDGES) return;

    int s = ei[e];
    int d = ei[E_EDGES + e];
    float w = ew[e];

    const float* src = (LAYER == 1) ? g_x : g_y;
    float*       dst = (LAYER == 1) ? g_agg1 : ext;

    float4 v = *(const float4*)(src + (size_t)s * EMB + c4);
    float* o = dst + (size_t)d * EMB + c4;
    asm volatile("red.global.add.v4.f32 [%0], {%1, %2, %3, %4};"
                 :: "l"(o), "f"(v.x * w), "f"(v.y * w), "f"(v.z * w), "f"(v.w * w)
                 : "memory");
}

// =========== HMMA bf16-split GEMM (mma.sync m16n8k16) ===========
// MODE 1: h[N,256] = relu([agg1|x] @ [W1_rel;W1_root] + b1)   K=256, Nout=256
// MODE 2: [y | out] = h @ [W2_rel | W2_root], out gets +b2     K=256, Nout=256
// CTA tile 128m x 128n (grid.y=2 over Nout). K in 8 chunks of 32.
// A,B split to bf16 hi/lo planes in smem; acc = AhiBhi + AhiBlo + AloBhi.

#define KSTR 40   // bf16 elems per smem row (32 + 8 pad, conflict-free)

template <int MODE>
__global__ __launch_bounds__(256, 2)
void gcn_gemm_mma(const float* __restrict__ Brel,
                  const float* __restrict__ Broot,
                  const float* __restrict__ bias,
                  float* __restrict__ dout)
{
    __shared__ __align__(16) uint16_t Ahi[128 * KSTR], Alo[128 * KSTR];
    __shared__ __align__(16) uint16_t Bhi[128 * KSTR], Blo[128 * KSTR];

    const int tid  = threadIdx.x;
    const int lane = tid & 31;
    const int wid  = tid >> 5;
    const int wm   = wid >> 1;        // 0..3 -> m offset wm*32
    const int wn   = wid & 1;         // 0..1 -> n offset wn*64
    const int m0   = blockIdx.x * 128;
    const int nb   = blockIdx.y;      // 0 or 1 (global n half)

    const uint32_t uAhi = smem_u32(Ahi), uAlo = smem_u32(Alo);
    const uint32_t uBhi = smem_u32(Bhi), uBlo = smem_u32(Blo);

    // ldmatrix lane offsets
    const int rA = (lane & 7) + ((lane >> 3) & 1) * 8;   // A row within m16
    const int kA = (lane >> 4) * 8;                      // A k-block
    const int rB = (lane & 7) + ((lane >> 4) & 1) * 8;   // B row within n16
    const int kB = ((lane >> 3) & 1) * 8;                // B k-block

    float acc[2][8][4];
    #pragma unroll
    for (int i = 0; i < 2; i++)
        #pragma unroll
        for (int j = 0; j < 8; j++)
            #pragma unroll
            for (int q = 0; q < 4; q++) acc[i][j][q] = 0.f;

    for (int kc = 0; kc < 8; kc++) {
        // ---- load+split A chunk: 128 rows x 32 k
        {
            const float* Asrc; int astr, kb;
            if (MODE == 1) { Asrc = (kc < 4) ? g_agg1 : g_x; astr = 128; kb = (kc & 3) * 32; }
            else           { Asrc = g_h;                     astr = 256; kb = kc * 32; }
            int r  = tid >> 1;
            int kh = (tid & 1) * 16;
            const float* ap = Asrc + (size_t)(m0 + r) * astr + kb + kh;
            #pragma unroll
            for (int i = 0; i < 4; i++) {
                float4 v = *(const float4*)(ap + i * 4);
                uint16_t h0, l0, h1, l1, h2, l2, h3, l3;
                split1(v.x, h0, l0); split1(v.y, h1, l1);
                split1(v.z, h2, l2); split1(v.w, h3, l3);
                int o = r * KSTR + kh + i * 4;
                uint2 hv = make_uint2((uint32_t)h0 | ((uint32_t)h1 << 16),
                                      (uint32_t)h2 | ((uint32_t)h3 << 16));
                uint2 lv = make_uint2((uint32_t)l0 | ((uint32_t)l1 << 16),
                                      (uint32_t)l2 | ((uint32_t)l3 << 16));
                *(uint2*)&Ahi[o] = hv;
                *(uint2*)&Alo[o] = lv;
            }
        }
        // ---- load+split+transpose B chunk: 32 k x 128 n  ->  smem [n][k]
        {
            int kr = lane;            // k row 0..31
            int nc = wid * 16;        // n chunk
            const float* bp;
            if (MODE == 1)
                bp = ((kc < 4) ? Brel : Broot) + (size_t)((kc & 3) * 32 + kr) * 256 + nb * 128 + nc;
            else
                bp = (nb ? Broot : Brel) + (size_t)(kc * 32 + kr) * 128 + nc;
            #pragma unroll
            for (int i = 0; i < 4; i++) {
                float4 v = *(const float4*)(bp + i * 4);
                uint16_t h, l;
                int n0l = nc + i * 4;
                split1(v.x, h, l); Bhi[(n0l + 0) * KSTR + kr] = h; Blo[(n0l + 0) * KSTR + kr] = l;
                split1(v.y, h, l); Bhi[(n0l + 1) * KSTR + kr] = h; Blo[(n0l + 1) * KSTR + kr] = l;
                split1(v.z, h, l); Bhi[(n0l + 2) * KSTR + kr] = h; Blo[(n0l + 2) * KSTR + kr] = l;
                split1(v.w, h, l); Bhi[(n0l + 3) * KSTR + kr] = h; Blo[(n0l + 3) * KSTR + kr] = l;
            }
        }
        __syncthreads();

        // ---- MMA: 2 ksteps of 16
        #pragma unroll
        for (int ks = 0; ks < 2; ks++) {
            uint32_t ahi[2][4], alo[2][4];
            #pragma unroll
            for (int mt = 0; mt < 2; mt++) {
                uint32_t off = ((uint32_t)((wm * 32 + mt * 16 + rA) * KSTR + ks * 16 + kA)) * 2;
                LDSM_X4(ahi[mt][0], ahi[mt][1], ahi[mt][2], ahi[mt][3], uAhi + off);
                LDSM_X4(alo[mt][0], alo[mt][1], alo[mt][2], alo[mt][3], uAlo + off);
            }
            #pragma unroll
            for (int np = 0; np < 4; np++) {   // pairs of n8 tiles
                uint32_t off = ((uint32_t)((wn * 64 + np * 16 + rB) * KSTR + ks * 16 + kB)) * 2;
                uint32_t bh[4], bl[4];
                LDSM_X4(bh[0], bh[1], bh[2], bh[3], uBhi + off);
                LDSM_X4(bl[0], bl[1], bl[2], bl[3], uBlo + off);
                #pragma unroll
                for (int mt = 0; mt < 2; mt++) {
                    MMA_BF16(acc[mt][np * 2 + 0], ahi[mt], bh[0], bh[1]);
                    MMA_BF16(acc[mt][np * 2 + 0], ahi[mt], bl[0], bl[1]);
                    MMA_BF16(acc[mt][np * 2 + 0], alo[mt], bh[0], bh[1]);
                    MMA_BF16(acc[mt][np * 2 + 1], ahi[mt], bh[2], bh[3]);
                    MMA_BF16(acc[mt][np * 2 + 1], ahi[mt], bl[2], bl[3]);
                    MMA_BF16(acc[mt][np * 2 + 1], alo[mt], bh[2], bh[3]);
                }
            }
        }
        __syncthreads();
    }

    // ---- epilogue: c-frag thread mapping: rows lane>>2 (+8), cols 2*(lane&3)
    const int rr = lane >> 2;
    const int cc = (lane & 3) * 2;
    #pragma unroll
    for (int mt = 0; mt < 2; mt++) {
        #pragma unroll
        for (int nt = 0; nt < 8; nt++) {
            int gm = m0 + wm * 32 + mt * 16 + rr;
            int nl = wn * 64 + nt * 8 + cc;          // 0..127 within this n-half
            if (MODE == 1) {
                int gN = nb * 128 + nl;
                float2 bv = *(const float2*)(bias + gN);
                float2 o0, o1;
                o0.x = fmaxf(acc[mt][nt][0] + bv.x, 0.f);
                o0.y = fmaxf(acc[mt][nt][1] + bv.y, 0.f);
                o1.x = fmaxf(acc[mt][nt][2] + bv.x, 0.f);
                o1.y = fmaxf(acc[mt][nt][3] + bv.y, 0.f);
                *(float2*)(g_h + (size_t)gm * 256 + gN)       = o0;
                *(float2*)(g_h + (size_t)(gm + 8) * 256 + gN) = o1;
            } else if (nb == 0) {
                *(float2*)(g_y + (size_t)gm * 128 + nl)       = make_float2(acc[mt][nt][0], acc[mt][nt][1]);
                *(float2*)(g_y + (size_t)(gm + 8) * 128 + nl) = make_float2(acc[mt][nt][2], acc[mt][nt][3]);
            } else {
                float2 bv = *(const float2*)(bias + nl);
                if (gm < NN)
                    *(float2*)(dout + (size_t)gm * 128 + nl) =
                        make_float2(acc[mt][nt][0] + bv.x, acc[mt][nt][1] + bv.y);
                if (gm + 8 < NN)
                    *(float2*)(dout + (size_t)(gm + 8) * 128 + nl) =
                        make_float2(acc[mt][nt][2] + bv.x, acc[mt][nt][3] + bv.y);
            }
        }
    }
}

// ---------------- launch ----------------
extern "C" void kernel_launch(void* const* d_in, const int* in_sizes, int n_in,
                              void* d_out, int out_size)
{
    const float* pol   = (const float*)d_in[0];
    const int*   sid   = (const int*)  d_in[1];
    const int*   ei    = (const int*)  d_in[2];
    const float* ew    = (const float*)d_in[3];
    const float* Wp    = (const float*)d_in[4];
    const float* bp    = (const float*)d_in[5];
    const float* semb  = (const float*)d_in[6];
    const float* tick  = (const float*)d_in[7];
    const float* W1rel = (const float*)d_in[8];
    const float* b1    = (const float*)d_in[9];
    const float* W1root= (const float*)d_in[10];
    const float* W2rel = (const float*)d_in[11];
    const float* b2    = (const float*)d_in[12];
    const float* W2root= (const float*)d_in[13];
    float* out = (float*)d_out;

    // 1) x build + zero agg1
    {
        int threads = NN * 32;
        build_x_kernel<<<(threads + 255) / 256, 256>>>(pol, sid, Wp, bp, semb, tick);
    }
    // 2) scatter layer 1: agg1[dst] += w * x[src]
    {
        long threads = (long)E_EDGES * 32;
        scatter_kernel<1><<<(int)((threads + 255) / 256), 256>>>(ei, ew, nullptr);
    }
    // 3) h = relu([agg1|x] @ [W1_rel;W1_root] + b1)
    {
        dim3 grid(NPAD / 128, 2);
        gcn_gemm_mma<1><<<grid, 256>>>(W1rel, W1root, b1, nullptr);
    }
    // 4) y = h @ W2_rel ; out = h @ W2_root + b2
    {
        dim3 grid(NPAD / 128, 2);
        gcn_gemm_mma<2><<<grid, 256>>>(W2rel, W2root, b2, out);
    }
    // 5) scatter layer 2 directly into out: out[dst] += w * y[src]
    {
        long threads = (long)E_EDGES * 32;
        scatter_kernel<2><<<(int)((threads + 255) / 256), 256>>>(ei, ew, out);
    }
}

// round 6
// speedup vs baseline: 2.0851x; 1.1710x over previous
#include <cuda_runtime.h>
#include <cuda_bf16.h>
#include <cstdint>

#define N_POL   100000
#define N_TICK  20000
#define NN      (N_POL + N_TICK)   // 120000
#define NPAD    120064             // 938 * 128
#define E_EDGES 1000000
#define POL_FEAT 7
#define EMB     128
#define HID     256
#define OUTD    128

// ---------------- scratch (static device globals; no allocation) ----------------
__device__ float    g_x[(size_t)NPAD * EMB];      // node features f32 (scatter src)
__device__ float    g_agg1[(size_t)NPAD * EMB];   // layer-1 aggregation (f32 atomics)
__device__ float    g_y[(size_t)NPAD * EMB];      // h @ W2_rel f32 (scatter src)
// pre-split bf16 planes
__device__ uint16_t g_xs_hi[(size_t)NPAD * EMB],  g_xs_lo[(size_t)NPAD * EMB];
__device__ uint16_t g_a1hi[(size_t)NPAD * EMB],   g_a1lo[(size_t)NPAD * EMB];
__device__ uint16_t g_hhi[(size_t)NPAD * HID],    g_hlo[(size_t)NPAD * HID];
__device__ uint16_t g_w1hi[256 * 256], g_w1lo[256 * 256];   // [n][k] (transposed)
__device__ uint16_t g_w2hi[256 * 256], g_w2lo[256 * 256];   // [n][k]

// ---------------- helpers ----------------
__device__ __forceinline__ uint32_t smem_u32(const void* p) {
    uint32_t a;
    asm("{ .reg .u64 t; cvta.to.shared.u64 t, %1; cvt.u32.u64 %0, t; }" : "=r"(a) : "l"(p));
    return a;
}
#define LDSM_X4(r0, r1, r2, r3, addr) \
    asm volatile("ldmatrix.sync.aligned.m8n8.x4.shared.b16 {%0,%1,%2,%3}, [%4];" \
        : "=r"(r0), "=r"(r1), "=r"(r2), "=r"(r3) : "r"(addr))
#define MMA_BF16(c, a, b0, b1) \
    asm volatile("mma.sync.aligned.m16n8k16.row.col.f32.bf16.bf16.f32 " \
        "{%0,%1,%2,%3}, {%4,%5,%6,%7}, {%8,%9}, {%0,%1,%2,%3};" \
        : "+f"((c)[0]), "+f"((c)[1]), "+f"((c)[2]), "+f"((c)[3]) \
        : "r"((a)[0]), "r"((a)[1]), "r"((a)[2]), "r"((a)[3]), "r"(b0), "r"(b1))
#define CP16(dst, src) \
    asm volatile("cp.async.cg.shared.global [%0], [%1], 16;" :: "r"(dst), "l"(src))
#define CP_COMMIT() asm volatile("cp.async.commit_group;" ::: "memory")
template <int N> __device__ __forceinline__ void cp_wait() {
    asm volatile("cp.async.wait_group %0;" :: "n"(N) : "memory");
}

__device__ __forceinline__ void split1(float v, uint16_t& h, uint16_t& l) {
    __nv_bfloat16 bh = __float2bfloat16(v);
    float fh = __bfloat162float(bh);
    __nv_bfloat16 bl = __float2bfloat16(v - fh);
    h = *reinterpret_cast<uint16_t*>(&bh);
    l = *reinterpret_cast<uint16_t*>(&bl);
}
__device__ __forceinline__ void split4(float4 v, uint2& hi, uint2& lo) {
    uint16_t h0, l0, h1, l1, h2, l2, h3, l3;
    split1(v.x, h0, l0); split1(v.y, h1, l1);
    split1(v.z, h2, l2); split1(v.w, h3, l3);
    hi = make_uint2((uint32_t)h0 | ((uint32_t)h1 << 16), (uint32_t)h2 | ((uint32_t)h3 << 16));
    lo = make_uint2((uint32_t)l0 | ((uint32_t)l1 << 16), (uint32_t)l2 | ((uint32_t)l3 << 16));
}

// ---------------- weight conversion: W -> [n][k] bf16 hi/lo planes ----------------
__global__ __launch_bounds__(256)
void wconv_kernel(const float* __restrict__ W1rel, const float* __restrict__ W1root,
                  const float* __restrict__ W2rel, const float* __restrict__ W2root)
{
    int idx = blockIdx.x * 256 + threadIdx.x;       // 0..131071
    int which = idx >> 16;
    int e = idx & 65535;
    int n = e >> 8, k = e & 255;
    float v;
    if (which == 0) v = (k < 128) ? W1rel[k * 256 + n] : W1root[(k - 128) * 256 + n];
    else            v = (n < 128) ? W2rel[k * 128 + n] : W2root[k * 128 + (n - 128)];
    uint16_t h, l;
    split1(v, h, l);
    if (which == 0) { g_w1hi[e] = h; g_w1lo[e] = l; }
    else            { g_w2hi[e] = h; g_w2lo[e] = l; }
}

// ---------------- build x (+split planes), zero agg1 ----------------
__global__ __launch_bounds__(256)
void build_x_kernel(const float* __restrict__ pol, const int* __restrict__ sid,
                    const float* __restrict__ Wp, const float* __restrict__ bp,
                    const float* __restrict__ semb, const float* __restrict__ tick)
{
    int t = blockIdx.x * blockDim.x + threadIdx.x;
    int node = t >> 5;
    int c4 = (t & 31) * 4;
    if (node >= NN) return;

    *(float4*)(g_agg1 + (size_t)node * EMB + c4) = make_float4(0.f, 0.f, 0.f, 0.f);

    float4 r;
    if (node < N_POL) {
        float4 acc = *(const float4*)(bp + c4);
        #pragma unroll
        for (int k = 0; k < POL_FEAT; k++) {
            float f = __ldg(pol + node * POL_FEAT + k);
            float4 w = *(const float4*)(Wp + k * EMB + c4);
            acc.x += f * w.x; acc.y += f * w.y; acc.z += f * w.z; acc.w += f * w.w;
        }
        int s = sid[node];
        float4 se = *(const float4*)(semb + (size_t)s * EMB + c4);
        r.x = fmaxf(acc.x, 0.f) + se.x;
        r.y = fmaxf(acc.y, 0.f) + se.y;
        r.z = fmaxf(acc.z, 0.f) + se.z;
        r.w = fmaxf(acc.w, 0.f) + se.w;
    } else {
        r = *(const float4*)(tick + (size_t)(node - N_POL) * EMB + c4);
    }
    *(float4*)(g_x + (size_t)node * EMB + c4) = r;
    uint2 hi, lo;
    split4(r, hi, lo);
    *(uint2*)&g_xs_hi[(size_t)node * EMB + c4] = hi;
    *(uint2*)&g_xs_lo[(size_t)node * EMB + c4] = lo;
}

// ---------------- convert agg1 -> bf16 hi/lo planes (after scatter1) ----------------
__global__ __launch_bounds__(256)
void conv_agg1_kernel()
{
    int t = blockIdx.x * blockDim.x + threadIdx.x;
    int node = t >> 5;
    int c4 = (t & 31) * 4;
    if (node >= NN) return;
    float4 v = *(const float4*)(g_agg1 + (size_t)node * EMB + c4);
    uint2 hi, lo;
    split4(v, hi, lo);
    *(uint2*)&g_a1hi[(size_t)node * EMB + c4] = hi;
    *(uint2*)&g_a1lo[(size_t)node * EMB + c4] = lo;
}

// ---------------- scatter: dst[d] += w * src[s], one warp per edge ----------------
template <int LAYER>
__global__ __launch_bounds__(256)
void scatter_kernel(const int* __restrict__ ei, const float* __restrict__ ew,
                    float* __restrict__ ext)
{
    int t = blockIdx.x * blockDim.x + threadIdx.x;
    int e = t >> 5;
    int c4 = (t & 31) * 4;
    if (e >= E_EDGES) return;

    int s = ei[e];
    int d = ei[E_EDGES + e];
    float w = ew[e];

    const float* src = (LAYER == 1) ? g_x : g_y;
    float*       dst = (LAYER == 1) ? g_agg1 : ext;

    float4 v = *(const float4*)(src + (size_t)s * EMB + c4);
    float* o = dst + (size_t)d * EMB + c4;
    asm volatile("red.global.add.v4.f32 [%0], {%1, %2, %3, %4};"
                 :: "l"(o), "f"(v.x * w), "f"(v.y * w), "f"(v.z * w), "f"(v.w * w)
                 : "memory");
}

// =========== HMMA bf16-split GEMM, pre-split operands + cp.async 2-stage pipeline ===========
// MODE 1: h = relu([agg1|x] @ [W1rel;W1root] + b1)  -> writes g_hhi/g_hlo (split)
// MODE 2: [y | out] = h @ [W2rel|W2root] (+b2 on out half)
// CTA tile 128m x 128n (grid.y = nb over 2 n-halves), K=256 in 8 chunks of 32.

#define KSTR   40                        // bf16 elems/row in smem (32 + 8 pad)
#define PLANE  (128 * KSTR * 2)          // 10240 B
#define STAGE  (4 * PLANE)               // Ahi,Alo,Bhi,Blo = 40960 B
#define SMTOT  (2 * STAGE)               // 81920 B

template <int MODE>
__global__ __launch_bounds__(256, 2)
void gcn_gemm_mma(const float* __restrict__ bias, float* __restrict__ dout)
{
    extern __shared__ char smem[];
    const uint32_t sb = smem_u32(smem);

    const int tid  = threadIdx.x;
    const int lane = tid & 31;
    const int wid  = tid >> 5;
    const int wm   = wid >> 1;
    const int wn   = wid & 1;
    const int m0   = blockIdx.x * 128;
    const int nb   = blockIdx.y;

    const uint16_t* whi = (MODE == 1) ? g_w1hi : g_w2hi;
    const uint16_t* wlo = (MODE == 1) ? g_w1lo : g_w2lo;

    // cp.async issue for chunk kc into stage st: 8 x 16B per thread
    auto issue = [&](int kc, int st) {
        const uint16_t *ahs, *als;
        int astr, kb;
        if (MODE == 1) {
            if (kc < 4) { ahs = g_a1hi; als = g_a1lo; }
            else        { ahs = g_xs_hi; als = g_xs_lo; }
            astr = 128; kb = (kc & 3) * 32;
        } else {
            ahs = g_hhi; als = g_hlo; astr = 256; kb = kc * 32;
        }
        uint32_t base = sb + st * STAGE;
        #pragma unroll
        for (int i = 0; i < 2; i++) {
            int cid = tid * 2 + i;       // 0..511
            int row = cid >> 2;
            int c   = cid & 3;           // 16B chunk within 64B row
            uint32_t doff = row * (KSTR * 2) + c * 16;
            CP16(base + 0 * PLANE + doff, ahs + (size_t)(m0 + row) * astr + kb + c * 8);
            CP16(base + 1 * PLANE + doff, als + (size_t)(m0 + row) * astr + kb + c * 8);
            const uint16_t* bh = whi + (size_t)(nb * 128 + row) * 256 + kc * 32 + c * 8;
            const uint16_t* bl = wlo + (size_t)(nb * 128 + row) * 256 + kc * 32 + c * 8;
            CP16(base + 2 * PLANE + doff, bh);
            CP16(base + 3 * PLANE + doff, bl);
        }
        CP_COMMIT();
    };

    // ldmatrix lane offsets
    const int rA = (lane & 7) + ((lane >> 3) & 1) * 8;
    const int kA = (lane >> 4) * 8;
    const int rB = (lane & 7) + ((lane >> 4) & 1) * 8;
    const int kB = ((lane >> 3) & 1) * 8;

    float acc[2][8][4];
    #pragma unroll
    for (int i = 0; i < 2; i++)
        #pragma unroll
        for (int j = 0; j < 8; j++)
            #pragma unroll
            for (int q = 0; q < 4; q++) acc[i][j][q] = 0.f;

    issue(0, 0);

    for (int kc = 0; kc < 8; kc++) {
        if (kc + 1 < 8) { issue(kc + 1, (kc + 1) & 1); cp_wait<1>(); }
        else            { cp_wait<0>(); }
        __syncthreads();

        uint32_t st = sb + (kc & 1) * STAGE;
        uint32_t uAhi = st, uAlo = st + PLANE, uBhi = st + 2 * PLANE, uBlo = st + 3 * PLANE;

        #pragma unroll
        for (int ks = 0; ks < 2; ks++) {
            uint32_t ahi[2][4], alo[2][4];
            #pragma unroll
            for (int mt = 0; mt < 2; mt++) {
                uint32_t off = ((uint32_t)((wm * 32 + mt * 16 + rA) * KSTR + ks * 16 + kA)) * 2;
                LDSM_X4(ahi[mt][0], ahi[mt][1], ahi[mt][2], ahi[mt][3], uAhi + off);
                LDSM_X4(alo[mt][0], alo[mt][1], alo[mt][2], alo[mt][3], uAlo + off);
            }
            #pragma unroll
            for (int np = 0; np < 4; np++) {
                uint32_t off = ((uint32_t)((wn * 64 + np * 16 + rB) * KSTR + ks * 16 + kB)) * 2;
                uint32_t bh[4], bl[4];
                LDSM_X4(bh[0], bh[1], bh[2], bh[3], uBhi + off);
                LDSM_X4(bl[0], bl[1], bl[2], bl[3], uBlo + off);
                #pragma unroll
                for (int mt = 0; mt < 2; mt++) {
                    MMA_BF16(acc[mt][np * 2 + 0], ahi[mt], bh[0], bh[1]);
                    MMA_BF16(acc[mt][np * 2 + 0], ahi[mt], bl[0], bl[1]);
                    MMA_BF16(acc[mt][np * 2 + 0], alo[mt], bh[0], bh[1]);
                    MMA_BF16(acc[mt][np * 2 + 1], ahi[mt], bh[2], bh[3]);
                    MMA_BF16(acc[mt][np * 2 + 1], ahi[mt], bl[2], bl[3]);
                    MMA_BF16(acc[mt][np * 2 + 1], alo[mt], bh[2], bh[3]);
                }
            }
        }
        __syncthreads();
    }

    // ---- epilogue
    const int rr = lane >> 2;
    const int cc = (lane & 3) * 2;
    #pragma unroll
    for (int mt = 0; mt < 2; mt++) {
        #pragma unroll
        for (int nt = 0; nt < 8; nt++) {
            int gm = m0 + wm * 32 + mt * 16 + rr;
            int nl = wn * 64 + nt * 8 + cc;
            if (MODE == 1) {
                int gN = nb * 128 + nl;
                float2 bv = *(const float2*)(bias + gN);
                float v00 = fmaxf(acc[mt][nt][0] + bv.x, 0.f);
                float v01 = fmaxf(acc[mt][nt][1] + bv.y, 0.f);
                float v10 = fmaxf(acc[mt][nt][2] + bv.x, 0.f);
                float v11 = fmaxf(acc[mt][nt][3] + bv.y, 0.f);
                uint16_t h0, l0, h1, l1;
                split1(v00, h0, l0); split1(v01, h1, l1);
                *(uint32_t*)&g_hhi[(size_t)gm * 256 + gN] = (uint32_t)h0 | ((uint32_t)h1 << 16);
                *(uint32_t*)&g_hlo[(size_t)gm * 256 + gN] = (uint32_t)l0 | ((uint32_t)l1 << 16);
                split1(v10, h0, l0); split1(v11, h1, l1);
                *(uint32_t*)&g_hhi[(size_t)(gm + 8) * 256 + gN] = (uint32_t)h0 | ((uint32_t)h1 << 16);
                *(uint32_t*)&g_hlo[(size_t)(gm + 8) * 256 + gN] = (uint32_t)l0 | ((uint32_t)l1 << 16);
            } else if (nb == 0) {
                *(float2*)(g_y + (size_t)gm * 128 + nl)       = make_float2(acc[mt][nt][0], acc[mt][nt][1]);
                *(float2*)(g_y + (size_t)(gm + 8) * 128 + nl) = make_float2(acc[mt][nt][2], acc[mt][nt][3]);
            } else {
                float2 bv = *(const float2*)(bias + nl);
                if (gm < NN)
                    *(float2*)(dout + (size_t)gm * 128 + nl) =
                        make_float2(acc[mt][nt][0] + bv.x, acc[mt][nt][1] + bv.y);
                if (gm + 8 < NN)
                    *(float2*)(dout + (size_t)(gm + 8) * 128 + nl) =
                        make_float2(acc[mt][nt][2] + bv.x, acc[mt][nt][3] + bv.y);
            }
        }
    }
}

// ---------------- launch ----------------
extern "C" void kernel_launch(void* const* d_in, const int* in_sizes, int n_in,
                              void* d_out, int out_size)
{
    const float* pol   = (const float*)d_in[0];
    const int*   sid   = (const int*)  d_in[1];
    const int*   ei    = (const int*)  d_in[2];
    const float* ew    = (const float*)d_in[3];
    const float* Wp    = (const float*)d_in[4];
    const float* bp    = (const float*)d_in[5];
    const float* semb  = (const float*)d_in[6];
    const float* tick  = (const float*)d_in[7];
    const float* W1rel = (const float*)d_in[8];
    const float* b1    = (const float*)d_in[9];
    const float* W1root= (const float*)d_in[10];
    const float* W2rel = (const float*)d_in[11];
    const float* b2    = (const float*)d_in[12];
    const float* W2root= (const float*)d_in[13];
    float* out = (float*)d_out;

    cudaFuncSetAttribute(gcn_gemm_mma<1>, cudaFuncAttributeMaxDynamicSharedMemorySize, SMTOT);
    cudaFuncSetAttribute(gcn_gemm_mma<2>, cudaFuncAttributeMaxDynamicSharedMemorySize, SMTOT);

    // 0) weight split planes
    wconv_kernel<<<512, 256>>>(W1rel, W1root, W2rel, W2root);
    // 1) x build (+split) + zero agg1
    {
        int threads = NN * 32;
        build_x_kernel<<<(threads + 255) / 256, 256>>>(pol, sid, Wp, bp, semb, tick);
    }
    // 2) scatter layer 1: agg1[dst] += w * x[src]
    {
        long threads = (long)E_EDGES * 32;
        scatter_kernel<1><<<(int)((threads + 255) / 256), 256>>>(ei, ew, nullptr);
    }
    // 2b) split agg1
    {
        int threads = NN * 32;
        conv_agg1_kernel<<<(threads + 255) / 256, 256>>>();
    }
    // 3) h = relu([agg1|x] @ [W1;W1root] + b1)  (writes split h planes)
    {
        dim3 grid(NPAD / 128, 2);
        gcn_gemm_mma<1><<<grid, 256, SMTOT>>>(b1, nullptr);
    }
    // 4) y = h @ W2rel ; out = h @ W2root + b2
    {
        dim3 grid(NPAD / 128, 2);
        gcn_gemm_mma<2><<<grid, 256, SMTOT>>>(b2, out);
    }
    // 5) scatter layer 2: out[dst] += w * y[src]
    {
        long threads = (long)E_EDGES * 32;
        scatter_kernel<2><<<(int)((threads + 255) / 256), 256>>>(ei, ew, out);
    }
}

// round 7
// speedup vs baseline: 2.1570x; 1.0345x over previous
#include <cuda_runtime.h>
#include <cuda_bf16.h>
#include <cstdint>

#define N_POL   100000
#define N_TICK  20000
#define NN      (N_POL + N_TICK)   // 120000
#define NPAD    120064             // 938 * 128
#define E_EDGES 1000000
#define POL_FEAT 7
#define EMB     128
#define HID     256
#define OUTD    128

// ---------------- scratch (static device globals; no allocation) ----------------
__device__ float    g_agg1[(size_t)NPAD * EMB];   // layer-1 aggregation (f32 atomics)
__device__ float    g_y[(size_t)NPAD * EMB];      // h @ W2_rel f32 (scatter src)
// pre-split bf16 planes
__device__ uint16_t g_xs_hi[(size_t)NPAD * EMB],  g_xs_lo[(size_t)NPAD * EMB];
__device__ uint16_t g_a1hi[(size_t)NPAD * EMB],   g_a1lo[(size_t)NPAD * EMB];
__device__ uint16_t g_hhi[(size_t)NPAD * HID],    g_hlo[(size_t)NPAD * HID];
__device__ uint16_t g_w1hi[256 * 256], g_w1lo[256 * 256];   // [n][k] (transposed)
__device__ uint16_t g_w2hi[256 * 256], g_w2lo[256 * 256];   // [n][k]

// ---------------- helpers ----------------
__device__ __forceinline__ uint32_t smem_u32(const void* p) {
    uint32_t a;
    asm("{ .reg .u64 t; cvta.to.shared.u64 t, %1; cvt.u32.u64 %0, t; }" : "=r"(a) : "l"(p));
    return a;
}
#define LDSM_X4(r0, r1, r2, r3, addr) \
    asm volatile("ldmatrix.sync.aligned.m8n8.x4.shared.b16 {%0,%1,%2,%3}, [%4];" \
        : "=r"(r0), "=r"(r1), "=r"(r2), "=r"(r3) : "r"(addr))
#define MMA_BF16(c, a, b0, b1) \
    asm volatile("mma.sync.aligned.m16n8k16.row.col.f32.bf16.bf16.f32 " \
        "{%0,%1,%2,%3}, {%4,%5,%6,%7}, {%8,%9}, {%0,%1,%2,%3};" \
        : "+f"((c)[0]), "+f"((c)[1]), "+f"((c)[2]), "+f"((c)[3]) \
        : "r"((a)[0]), "r"((a)[1]), "r"((a)[2]), "r"((a)[3]), "r"(b0), "r"(b1))
#define CP16(dst, src) \
    asm volatile("cp.async.cg.shared.global [%0], [%1], 16;" :: "r"(dst), "l"(src))
#define CP_COMMIT() asm volatile("cp.async.commit_group;" ::: "memory")
template <int N> __device__ __forceinline__ void cp_wait() {
    asm volatile("cp.async.wait_group %0;" :: "n"(N) : "memory");
}

__device__ __forceinline__ void split1(float v, uint16_t& h, uint16_t& l) {
    __nv_bfloat16 bh = __float2bfloat16(v);
    float fh = __bfloat162float(bh);
    __nv_bfloat16 bl = __float2bfloat16(v - fh);
    h = *reinterpret_cast<uint16_t*>(&bh);
    l = *reinterpret_cast<uint16_t*>(&bl);
}
__device__ __forceinline__ void split4(float4 v, uint2& hi, uint2& lo) {
    uint16_t h0, l0, h1, l1, h2, l2, h3, l3;
    split1(v.x, h0, l0); split1(v.y, h1, l1);
    split1(v.z, h2, l2); split1(v.w, h3, l3);
    hi = make_uint2((uint32_t)h0 | ((uint32_t)h1 << 16), (uint32_t)h2 | ((uint32_t)h3 << 16));
    lo = make_uint2((uint32_t)l0 | ((uint32_t)l1 << 16), (uint32_t)l2 | ((uint32_t)l3 << 16));
}

// ---------------- weight conversion: W -> [n][k] bf16 hi/lo planes ----------------
__global__ __launch_bounds__(256)
void wconv_kernel(const float* __restrict__ W1rel, const float* __restrict__ W1root,
                  const float* __restrict__ W2rel, const float* __restrict__ W2root)
{
    int idx = blockIdx.x * 256 + threadIdx.x;       // 0..131071
    int which = idx >> 16;
    int e = idx & 65535;
    int n = e >> 8, k = e & 255;
    float v;
    if (which == 0) v = (k < 128) ? W1rel[k * 256 + n] : W1root[(k - 128) * 256 + n];
    else            v = (n < 128) ? W2rel[k * 128 + n] : W2root[k * 128 + (n - 128)];
    uint16_t h, l;
    split1(v, h, l);
    if (which == 0) { g_w1hi[e] = h; g_w1lo[e] = l; }
    else            { g_w2hi[e] = h; g_w2lo[e] = l; }
}

// ---------------- build x split planes, zero agg1 ----------------
__global__ __launch_bounds__(256)
void build_x_kernel(const float* __restrict__ pol, const int* __restrict__ sid,
                    const float* __restrict__ Wp, const float* __restrict__ bp,
                    const float* __restrict__ semb, const float* __restrict__ tick)
{
    int t = blockIdx.x * blockDim.x + threadIdx.x;
    int node = t >> 5;
    int c4 = (t & 31) * 4;
    if (node >= NN) return;

    *(float4*)(g_agg1 + (size_t)node * EMB + c4) = make_float4(0.f, 0.f, 0.f, 0.f);

    float4 r;
    if (node < N_POL) {
        float4 acc = *(const float4*)(bp + c4);
        #pragma unroll
        for (int k = 0; k < POL_FEAT; k++) {
            float f = __ldg(pol + node * POL_FEAT + k);
            float4 w = *(const float4*)(Wp + k * EMB + c4);
            acc.x += f * w.x; acc.y += f * w.y; acc.z += f * w.z; acc.w += f * w.w;
        }
        int s = sid[node];
        float4 se = *(const float4*)(semb + (size_t)s * EMB + c4);
        r.x = fmaxf(acc.x, 0.f) + se.x;
        r.y = fmaxf(acc.y, 0.f) + se.y;
        r.z = fmaxf(acc.z, 0.f) + se.z;
        r.w = fmaxf(acc.w, 0.f) + se.w;
    } else {
        r = *(const float4*)(tick + (size_t)(node - N_POL) * EMB + c4);
    }
    uint2 hi, lo;
    split4(r, hi, lo);
    *(uint2*)&g_xs_hi[(size_t)node * EMB + c4] = hi;
    *(uint2*)&g_xs_lo[(size_t)node * EMB + c4] = lo;
}

// ---------------- convert agg1 -> bf16 hi/lo planes (after scatter1) ----------------
__global__ __launch_bounds__(256)
void conv_agg1_kernel()
{
    int t = blockIdx.x * blockDim.x + threadIdx.x;
    int node = t >> 5;
    int c4 = (t & 31) * 4;
    if (node >= NN) return;
    float4 v = *(const float4*)(g_agg1 + (size_t)node * EMB + c4);
    uint2 hi, lo;
    split4(v, hi, lo);
    *(uint2*)&g_a1hi[(size_t)node * EMB + c4] = hi;
    *(uint2*)&g_a1lo[(size_t)node * EMB + c4] = lo;
}

// ---------------- scatter: dst[d] += w * src[s], one warp per edge ----------------
// LAYER 1: src = x reconstructed from bf16 planes, dst = g_agg1
// LAYER 2: src = g_y (f32), dst = ext (d_out)
template <int LAYER>
__global__ __launch_bounds__(256)
void scatter_kernel(const int* __restrict__ ei, const float* __restrict__ ew,
                    float* __restrict__ ext)
{
    int t = blockIdx.x * blockDim.x + threadIdx.x;
    int e = t >> 5;
    int c4 = (t & 31) * 4;
    if (e >= E_EDGES) return;

    int s = ei[e];
    int d = ei[E_EDGES + e];
    float w = ew[e];

    float4 v;
    if (LAYER == 1) {
        uint2 h = *(const uint2*)(g_xs_hi + (size_t)s * EMB + c4);
        uint2 l = *(const uint2*)(g_xs_lo + (size_t)s * EMB + c4);
        float2 a0 = __bfloat1622float2(*reinterpret_cast<__nv_bfloat162*>(&h.x));
        float2 b0 = __bfloat1622float2(*reinterpret_cast<__nv_bfloat162*>(&l.x));
        float2 a1 = __bfloat1622float2(*reinterpret_cast<__nv_bfloat162*>(&h.y));
        float2 b1 = __bfloat1622float2(*reinterpret_cast<__nv_bfloat162*>(&l.y));
        v = make_float4(a0.x + b0.x, a0.y + b0.y, a1.x + b1.x, a1.y + b1.y);
    } else {
        v = *(const float4*)(g_y + (size_t)s * EMB + c4);
    }

    float* o = ((LAYER == 1) ? g_agg1 : ext) + (size_t)d * EMB + c4;
    asm volatile("red.global.add.v4.f32 [%0], {%1, %2, %3, %4};"
                 :: "l"(o), "f"(v.x * w), "f"(v.y * w), "f"(v.z * w), "f"(v.w * w)
                 : "memory");
}

// =========== persistent-B HMMA bf16-split GEMM ===========
// 296 CTAs (2/SM, one wave). CTA owns n-quarter q (64 cols), loads B planes once,
// loops over m-tiles (128 rows) streaming A via 2-stage cp.async pipeline.
// MODE 1: h = relu([agg1|x] @ [W1rel;W1root] + b1) -> g_hhi/g_hlo (split)
// MODE 2: [y | out] = h @ [W2rel|W2root] (+b2 on out half)

#define A_KSTR  40
#define A_PLANE (128 * A_KSTR * 2)        // 10240
#define A_STAGE (2 * A_PLANE)             // 20480 (hi+lo)
#define B_KSTR  264
#define B_PLANE (64 * B_KSTR * 2)         // 33792
#define SM_A    (2 * B_PLANE)             // 67584
#define SMTOT   (SM_A + 2 * A_STAGE)      // 108544
#define NSLOT   74                        // 296 / 4 quarters

template <int MODE>
__global__ __launch_bounds__(256, 2)
void gcn_gemm_mma(const float* __restrict__ bias, float* __restrict__ dout)
{
    extern __shared__ char smem[];
    const uint32_t sb = smem_u32(smem);

    const int tid  = threadIdx.x;
    const int lane = tid & 31;
    const int wid  = tid >> 5;
    const int wm   = wid >> 1;          // 0..3: m offset wm*32
    const int wn   = wid & 1;           // 0..1: n offset wn*32
    const int q    = blockIdx.x & 3;    // n-quarter (global n = q*64 + ...)
    const int slot = blockIdx.x >> 2;   // 0..73

    const uint16_t* whi = (MODE == 1) ? g_w1hi : g_w2hi;
    const uint16_t* wlo = (MODE == 1) ? g_w1lo : g_w2lo;

    // ---- load B quarter once: [64 n][256 k] hi/lo
    #pragma unroll
    for (int i = 0; i < 16; i++) {
        int c = i * 256 + tid;            // 0..4095
        int plane = c >> 11;
        int rem = c & 2047;
        int row = rem >> 5;               // 0..63
        int col = rem & 31;               // 16B chunk (8 bf16)
        const uint16_t* src = (plane ? wlo : whi) + (size_t)(q * 64 + row) * 256 + col * 8;
        uint32_t dst = sb + plane * B_PLANE + (uint32_t)(row * B_KSTR + col * 8) * 2;
        CP16(dst, src);
    }
    CP_COMMIT();
    cp_wait<0>();
    __syncthreads();

    // A-chunk issue: chunk kc (32 k) of m-tile m0 into stage st
    auto issue = [&](int m0, int kc, int st) {
        const uint16_t *ahs, *als;
        int astr, kb;
        if (MODE == 1) {
            if (kc < 4) { ahs = g_a1hi;  als = g_a1lo; }
            else        { ahs = g_xs_hi; als = g_xs_lo; }
            astr = 128; kb = (kc & 3) * 32;
        } else {
            ahs = g_hhi; als = g_hlo; astr = 256; kb = kc * 32;
        }
        uint32_t base = sb + SM_A + st * A_STAGE;
        #pragma unroll
        for (int i = 0; i < 4; i++) {
            int c = i * 256 + tid;          // 0..1023
            int plane = c >> 9;
            int rem = c & 511;
            int row = rem >> 2;             // 0..127
            int col = rem & 3;              // 16B chunk
            const uint16_t* src = (plane ? als : ahs) + (size_t)(m0 + row) * astr + kb + col * 8;
            uint32_t dst = base + plane * A_PLANE + (uint32_t)(row * A_KSTR + col * 8) * 2;
            CP16(dst, src);
        }
        CP_COMMIT();
    };

    // ldmatrix lane offsets
    const int rA = (lane & 7) + ((lane >> 3) & 1) * 8;
    const int kA = (lane >> 4) * 8;
    const int rB = (lane & 7) + ((lane >> 4) & 1) * 8;
    const int kB = ((lane >> 3) & 1) * 8;
    const int rr = lane >> 2;
    const int cc = (lane & 3) * 2;

    for (int t = slot; t < NPAD / 128; t += NSLOT) {
        const int m0 = t * 128;

        float acc[2][4][4];
        #pragma unroll
        for (int i = 0; i < 2; i++)
            #pragma unroll
            for (int j = 0; j < 4; j++)
                #pragma unroll
                for (int p = 0; p < 4; p++) acc[i][j][p] = 0.f;

        issue(m0, 0, 0);

        for (int kc = 0; kc < 8; kc++) {
            if (kc + 1 < 8) { issue(m0, kc + 1, (kc + 1) & 1); cp_wait<1>(); }
            else            { cp_wait<0>(); }
            __syncthreads();

            uint32_t uA = sb + SM_A + (kc & 1) * A_STAGE;
            uint32_t uAhi = uA, uAlo = uA + A_PLANE;

            #pragma unroll
            for (int ks = 0; ks < 2; ks++) {
                uint32_t ahi[2][4], alo[2][4];
                #pragma unroll
                for (int mt = 0; mt < 2; mt++) {
                    uint32_t off = ((uint32_t)((wm * 32 + mt * 16 + rA) * A_KSTR + ks * 16 + kA)) * 2;
                    LDSM_X4(ahi[mt][0], ahi[mt][1], ahi[mt][2], ahi[mt][3], uAhi + off);
                    LDSM_X4(alo[mt][0], alo[mt][1], alo[mt][2], alo[mt][3], uAlo + off);
                }
                #pragma unroll
                for (int np = 0; np < 2; np++) {
                    uint32_t boff = ((uint32_t)((wn * 32 + np * 16 + rB) * B_KSTR + kc * 32 + ks * 16 + kB)) * 2;
                    uint32_t bh[4], bl[4];
                    LDSM_X4(bh[0], bh[1], bh[2], bh[3], sb + boff);
                    LDSM_X4(bl[0], bl[1], bl[2], bl[3], sb + B_PLANE + boff);
                    #pragma unroll
                    for (int mt = 0; mt < 2; mt++) {
                        MMA_BF16(acc[mt][np * 2 + 0], ahi[mt], bh[0], bh[1]);
                        MMA_BF16(acc[mt][np * 2 + 0], ahi[mt], bl[0], bl[1]);
                        MMA_BF16(acc[mt][np * 2 + 0], alo[mt], bh[0], bh[1]);
                        MMA_BF16(acc[mt][np * 2 + 1], ahi[mt], bh[2], bh[3]);
                        MMA_BF16(acc[mt][np * 2 + 1], ahi[mt], bl[2], bl[3]);
                        MMA_BF16(acc[mt][np * 2 + 1], alo[mt], bh[2], bh[3]);
                    }
                }
            }
            __syncthreads();
        }

        // ---- epilogue for this m-tile
        #pragma unroll
        for (int mt = 0; mt < 2; mt++) {
            #pragma unroll
            for (int j = 0; j < 4; j++) {
                int gm = m0 + wm * 32 + mt * 16 + rr;
                int gN = q * 64 + wn * 32 + j * 8 + cc;
                if (MODE == 1) {
                    float2 bv = *(const float2*)(bias + gN);
                    float v00 = fmaxf(acc[mt][j][0] + bv.x, 0.f);
                    float v01 = fmaxf(acc[mt][j][1] + bv.y, 0.f);
                    float v10 = fmaxf(acc[mt][j][2] + bv.x, 0.f);
                    float v11 = fmaxf(acc[mt][j][3] + bv.y, 0.f);
                    uint16_t h0, l0, h1, l1;
                    split1(v00, h0, l0); split1(v01, h1, l1);
                    *(uint32_t*)&g_hhi[(size_t)gm * 256 + gN] = (uint32_t)h0 | ((uint32_t)h1 << 16);
                    *(uint32_t*)&g_hlo[(size_t)gm * 256 + gN] = (uint32_t)l0 | ((uint32_t)l1 << 16);
                    split1(v10, h0, l0); split1(v11, h1, l1);
                    *(uint32_t*)&g_hhi[(size_t)(gm + 8) * 256 + gN] = (uint32_t)h0 | ((uint32_t)h1 << 16);
                    *(uint32_t*)&g_hlo[(size_t)(gm + 8) * 256 + gN] = (uint32_t)l0 | ((uint32_t)l1 << 16);
                } else if (gN < 128) {
                    *(float2*)(g_y + (size_t)gm * 128 + gN)       = make_float2(acc[mt][j][0], acc[mt][j][1]);
                    *(float2*)(g_y + (size_t)(gm + 8) * 128 + gN) = make_float2(acc[mt][j][2], acc[mt][j][3]);
                } else {
                    int nc = gN - 128;
                    float2 bv = *(const float2*)(bias + nc);
                    if (gm < NN)
                        *(float2*)(dout + (size_t)gm * 128 + nc) =
                            make_float2(acc[mt][j][0] + bv.x, acc[mt][j][1] + bv.y);
                    if (gm + 8 < NN)
                        *(float2*)(dout + (size_t)(gm + 8) * 128 + nc) =
                            make_float2(acc[mt][j][2] + bv.x, acc[mt][j][3] + bv.y);
                }
            }
        }
    }
}

// ---------------- launch ----------------
extern "C" void kernel_launch(void* const* d_in, const int* in_sizes, int n_in,
                              void* d_out, int out_size)
{
    const float* pol   = (const float*)d_in[0];
    const int*   sid   = (const int*)  d_in[1];
    const int*   ei    = (const int*)  d_in[2];
    const float* ew    = (const float*)d_in[3];
    const float* Wp    = (const float*)d_in[4];
    const float* bp    = (const float*)d_in[5];
    const float* semb  = (const float*)d_in[6];
    const float* tick  = (const float*)d_in[7];
    const float* W1rel = (const float*)d_in[8];
    const float* b1    = (const float*)d_in[9];
    const float* W1root= (const float*)d_in[10];
    const float* W2rel = (const float*)d_in[11];
    const float* b2    = (const float*)d_in[12];
    const float* W2root= (const float*)d_in[13];
    float* out = (float*)d_out;

    cudaFuncSetAttribute(gcn_gemm_mma<1>, cudaFuncAttributeMaxDynamicSharedMemorySize, SMTOT);
    cudaFuncSetAttribute(gcn_gemm_mma<2>, cudaFuncAttributeMaxDynamicSharedMemorySize, SMTOT);

    // 0) weight split planes
    wconv_kernel<<<512, 256>>>(W1rel, W1root, W2rel, W2root);
    // 1) x build (split planes) + zero agg1
    {
        int threads = NN * 32;
        build_x_kernel<<<(threads + 255) / 256, 256>>>(pol, sid, Wp, bp, semb, tick);
    }
    // 2) scatter layer 1: agg1[dst] += w * x[src]
    {
        long threads = (long)E_EDGES * 32;
        scatter_kernel<1><<<(int)((threads + 255) / 256), 256>>>(ei, ew, nullptr);
    }
    // 2b) split agg1
    {
        int threads = NN * 32;
        conv_agg1_kernel<<<(threads + 255) / 256, 256>>>();
    }
    // 3) h = relu([agg1|x] @ [W1;W1root] + b1)  (writes split h planes)
    gcn_gemm_mma<1><<<4 * NSLOT, 256, SMTOT>>>(b1, nullptr);
    // 4) y = h @ W2rel ; out = h @ W2root + b2
    gcn_gemm_mma<2><<<4 * NSLOT, 256, SMTOT>>>(b2, out);
    // 5) scatter layer 2: out[dst] += w * y[src]
    {
        long threads = (long)E_EDGES * 32;
        scatter_kernel<2><<<(int)((threads + 255) / 256), 256>>>(ei, ew, out);
    }
}

// round 8
// speedup vs baseline: 2.7542x; 1.2769x over previous
#include <cuda_runtime.h>
#include <cuda_bf16.h>
#include <cstdint>

#define N_POL   100000
#define N_TICK  20000
#define NN      (N_POL + N_TICK)   // 120000
#define NPAD    120064             // 469 * 256
#define NB1     469
#define E_EDGES 1000000
#define POL_FEAT 7
#define EMB     128
#define HID     256
#define OUTD    128

// ---------------- scratch (static device globals; no allocation) ----------------
__device__ float    g_y[(size_t)NPAD * EMB];      // h @ W2_rel f32 (gather src)
// pre-split bf16 planes
__device__ uint16_t g_xs_hi[(size_t)NPAD * EMB],  g_xs_lo[(size_t)NPAD * EMB];
__device__ uint16_t g_a1hi[(size_t)NPAD * EMB],   g_a1lo[(size_t)NPAD * EMB];
__device__ uint16_t g_hhi[(size_t)NPAD * HID],    g_hlo[(size_t)NPAD * HID];
__device__ uint16_t g_w1hi[256 * 256], g_w1lo[256 * 256];   // [n][k]
__device__ uint16_t g_w2hi[256 * 256], g_w2lo[256 * 256];   // [n][k]
// CSR structures
__device__ int  g_cnt[NPAD];
__device__ int  g_off[NPAD];
__device__ int  g_cur[NPAD];
__device__ int  g_bsum[NB1];
__device__ int  g_boff[NB1];
__device__ int2 g_edge[E_EDGES];    // {src, weight_bits} sorted by dst

// ---------------- helpers ----------------
__device__ __forceinline__ uint32_t smem_u32(const void* p) {
    uint32_t a;
    asm("{ .reg .u64 t; cvta.to.shared.u64 t, %1; cvt.u32.u64 %0, t; }" : "=r"(a) : "l"(p));
    return a;
}
#define LDSM_X4(r0, r1, r2, r3, addr) \
    asm volatile("ldmatrix.sync.aligned.m8n8.x4.shared.b16 {%0,%1,%2,%3}, [%4];" \
        : "=r"(r0), "=r"(r1), "=r"(r2), "=r"(r3) : "r"(addr))
#define MMA_BF16(c, a, b0, b1) \
    asm volatile("mma.sync.aligned.m16n8k16.row.col.f32.bf16.bf16.f32 " \
        "{%0,%1,%2,%3}, {%4,%5,%6,%7}, {%8,%9}, {%0,%1,%2,%3};" \
        : "+f"((c)[0]), "+f"((c)[1]), "+f"((c)[2]), "+f"((c)[3]) \
        : "r"((a)[0]), "r"((a)[1]), "r"((a)[2]), "r"((a)[3]), "r"(b0), "r"(b1))
#define CP16(dst, src) \
    asm volatile("cp.async.cg.shared.global [%0], [%1], 16;" :: "r"(dst), "l"(src))
#define CP_COMMIT() asm volatile("cp.async.commit_group;" ::: "memory")
template <int N> __device__ __forceinline__ void cp_wait() {
    asm volatile("cp.async.wait_group %0;" :: "n"(N) : "memory");
}

__device__ __forceinline__ void split1(float v, uint16_t& h, uint16_t& l) {
    __nv_bfloat16 bh = __float2bfloat16(v);
    float fh = __bfloat162float(bh);
    __nv_bfloat16 bl = __float2bfloat16(v - fh);
    h = *reinterpret_cast<uint16_t*>(&bh);
    l = *reinterpret_cast<uint16_t*>(&bl);
}
__device__ __forceinline__ void split4(float4 v, uint2& hi, uint2& lo) {
    uint16_t h0, l0, h1, l1, h2, l2, h3, l3;
    split1(v.x, h0, l0); split1(v.y, h1, l1);
    split1(v.z, h2, l2); split1(v.w, h3, l3);
    hi = make_uint2((uint32_t)h0 | ((uint32_t)h1 << 16), (uint32_t)h2 | ((uint32_t)h3 << 16));
    lo = make_uint2((uint32_t)l0 | ((uint32_t)l1 << 16), (uint32_t)l2 | ((uint32_t)l3 << 16));
}
__device__ __forceinline__ float4 recon4(uint2 h, uint2 l) {
    float2 a0 = __bfloat1622float2(*reinterpret_cast<__nv_bfloat162*>(&h.x));
    float2 b0 = __bfloat1622float2(*reinterpret_cast<__nv_bfloat162*>(&l.x));
    float2 a1 = __bfloat1622float2(*reinterpret_cast<__nv_bfloat162*>(&h.y));
    float2 b1 = __bfloat1622float2(*reinterpret_cast<__nv_bfloat162*>(&l.y));
    return make_float4(a0.x + b0.x, a0.y + b0.y, a1.x + b1.x, a1.y + b1.y);
}

// ---------------- weight conversion ----------------
__global__ __launch_bounds__(256)
void wconv_kernel(const float* __restrict__ W1rel, const float* __restrict__ W1root,
                  const float* __restrict__ W2rel, const float* __restrict__ W2root)
{
    int idx = blockIdx.x * 256 + threadIdx.x;
    int which = idx >> 16;
    int e = idx & 65535;
    int n = e >> 8, k = e & 255;
    float v;
    if (which == 0) v = (k < 128) ? W1rel[k * 256 + n] : W1root[(k - 128) * 256 + n];
    else            v = (n < 128) ? W2rel[k * 128 + n] : W2root[k * 128 + (n - 128)];
    uint16_t h, l;
    split1(v, h, l);
    if (which == 0) { g_w1hi[e] = h; g_w1lo[e] = l; }
    else            { g_w2hi[e] = h; g_w2lo[e] = l; }
}

// ---------------- CSR build kernels ----------------
__global__ __launch_bounds__(256)
void zero_cnt_kernel()
{
    int idx = blockIdx.x * 256 + threadIdx.x;
    if (idx < NPAD / 4) ((int4*)g_cnt)[idx] = make_int4(0, 0, 0, 0);
}

__global__ __launch_bounds__(256)
void hist_kernel(const int* __restrict__ ei)
{
    int e = blockIdx.x * 256 + threadIdx.x;
    if (e < E_EDGES) atomicAdd(&g_cnt[ei[E_EDGES + e]], 1);
}

__global__ __launch_bounds__(256)
void scan1_kernel()
{
    __shared__ int s[256];
    int tid = threadIdx.x;
    int idx = blockIdx.x * 256 + tid;
    int v = g_cnt[idx];
    s[tid] = v;
    __syncthreads();
    #pragma unroll
    for (int d = 1; d < 256; d <<= 1) {
        int t = (tid >= d) ? s[tid - d] : 0;
        __syncthreads();
        s[tid] += t;
        __syncthreads();
    }
    g_off[idx] = s[tid] - v;                  // block-local exclusive
    if (tid == 255) g_bsum[blockIdx.x] = s[255];
}

__global__ __launch_bounds__(512)
void scan2_kernel()
{
    __shared__ int s[512];
    int tid = threadIdx.x;
    int v = (tid < NB1) ? g_bsum[tid] : 0;
    s[tid] = v;
    __syncthreads();
    #pragma unroll
    for (int d = 1; d < 512; d <<= 1) {
        int t = (tid >= d) ? s[tid - d] : 0;
        __syncthreads();
        s[tid] += t;
        __syncthreads();
    }
    if (tid < NB1) g_boff[tid] = s[tid] - v;  // exclusive block offsets
}

__global__ __launch_bounds__(256)
void scan3_kernel()
{
    int idx = blockIdx.x * 256 + threadIdx.x;
    int o = g_off[idx] + g_boff[blockIdx.x];
    g_off[idx] = o;
    g_cur[idx] = o;
}

__global__ __launch_bounds__(256)
void place_kernel(const int* __restrict__ ei, const float* __restrict__ ew)
{
    int e = blockIdx.x * 256 + threadIdx.x;
    if (e >= E_EDGES) return;
    int s = ei[e];
    int d = ei[E_EDGES + e];
    float w = ew[e];
    int pos = atomicAdd(&g_cur[d], 1);
    g_edge[pos] = make_int2(s, __float_as_int(w));
}

// ---------------- build x split planes ----------------
__global__ __launch_bounds__(256)
void build_x_kernel(const float* __restrict__ pol, const int* __restrict__ sid,
                    const float* __restrict__ Wp, const float* __restrict__ bp,
                    const float* __restrict__ semb, const float* __restrict__ tick)
{
    int t = blockIdx.x * blockDim.x + threadIdx.x;
    int node = t >> 5;
    int c4 = (t & 31) * 4;
    if (node >= NN) return;

    float4 r;
    if (node < N_POL) {
        float4 acc = *(const float4*)(bp + c4);
        #pragma unroll
        for (int k = 0; k < POL_FEAT; k++) {
            float f = __ldg(pol + node * POL_FEAT + k);
            float4 w = *(const float4*)(Wp + k * EMB + c4);
            acc.x += f * w.x; acc.y += f * w.y; acc.z += f * w.z; acc.w += f * w.w;
        }
        int s = sid[node];
        float4 se = *(const float4*)(semb + (size_t)s * EMB + c4);
        r.x = fmaxf(acc.x, 0.f) + se.x;
        r.y = fmaxf(acc.y, 0.f) + se.y;
        r.z = fmaxf(acc.z, 0.f) + se.z;
        r.w = fmaxf(acc.w, 0.f) + se.w;
    } else {
        r = *(const float4*)(tick + (size_t)(node - N_POL) * EMB + c4);
    }
    uint2 hi, lo;
    split4(r, hi, lo);
    *(uint2*)&g_xs_hi[(size_t)node * EMB + c4] = hi;
    *(uint2*)&g_xs_lo[(size_t)node * EMB + c4] = lo;
}

// ---------------- gather1: agg1 planes = split( sum_e w * x[src] ) ----------------
__global__ __launch_bounds__(256)
void gather1_kernel()
{
    int t = blockIdx.x * blockDim.x + threadIdx.x;
    int node = t >> 5;
    int c4 = (t & 31) * 4;
    if (node >= NN) return;

    int cnt = __ldg(&g_cnt[node]);
    int off = __ldg(&g_off[node]);

    float4 acc = make_float4(0.f, 0.f, 0.f, 0.f);
    int i = 0;
    for (; i + 1 < cnt; i += 2) {
        int2 e0 = __ldg(&g_edge[off + i]);
        int2 e1 = __ldg(&g_edge[off + i + 1]);
        uint2 h0 = *(const uint2*)&g_xs_hi[(size_t)e0.x * EMB + c4];
        uint2 l0 = *(const uint2*)&g_xs_lo[(size_t)e0.x * EMB + c4];
        uint2 h1 = *(const uint2*)&g_xs_hi[(size_t)e1.x * EMB + c4];
        uint2 l1 = *(const uint2*)&g_xs_lo[(size_t)e1.x * EMB + c4];
        float w0 = __int_as_float(e0.y);
        float w1 = __int_as_float(e1.y);
        float4 v0 = recon4(h0, l0);
        float4 v1 = recon4(h1, l1);
        acc.x += w0 * v0.x + w1 * v1.x;
        acc.y += w0 * v0.y + w1 * v1.y;
        acc.z += w0 * v0.z + w1 * v1.z;
        acc.w += w0 * v0.w + w1 * v1.w;
    }
    if (i < cnt) {
        int2 e0 = __ldg(&g_edge[off + i]);
        uint2 h0 = *(const uint2*)&g_xs_hi[(size_t)e0.x * EMB + c4];
        uint2 l0 = *(const uint2*)&g_xs_lo[(size_t)e0.x * EMB + c4];
        float w0 = __int_as_float(e0.y);
        float4 v0 = recon4(h0, l0);
        acc.x += w0 * v0.x; acc.y += w0 * v0.y;
        acc.z += w0 * v0.z; acc.w += w0 * v0.w;
    }

    uint2 hi, lo;
    split4(acc, hi, lo);
    *(uint2*)&g_a1hi[(size_t)node * EMB + c4] = hi;
    *(uint2*)&g_a1lo[(size_t)node * EMB + c4] = lo;
}

// ---------------- gather2: out += sum_e w * y[src] ----------------
__global__ __launch_bounds__(256)
void gather2_kernel(float* __restrict__ out)
{
    int t = blockIdx.x * blockDim.x + threadIdx.x;
    int node = t >> 5;
    int c4 = (t & 31) * 4;
    if (node >= NN) return;

    int cnt = __ldg(&g_cnt[node]);
    if (cnt == 0) return;
    int off = __ldg(&g_off[node]);

    float4 acc = make_float4(0.f, 0.f, 0.f, 0.f);
    int i = 0;
    for (; i + 1 < cnt; i += 2) {
        int2 e0 = __ldg(&g_edge[off + i]);
        int2 e1 = __ldg(&g_edge[off + i + 1]);
        float4 v0 = *(const float4*)(g_y + (size_t)e0.x * EMB + c4);
        float4 v1 = *(const float4*)(g_y + (size_t)e1.x * EMB + c4);
        float w0 = __int_as_float(e0.y);
        float w1 = __int_as_float(e1.y);
        acc.x += w0 * v0.x + w1 * v1.x;
        acc.y += w0 * v0.y + w1 * v1.y;
        acc.z += w0 * v0.z + w1 * v1.z;
        acc.w += w0 * v0.w + w1 * v1.w;
    }
    if (i < cnt) {
        int2 e0 = __ldg(&g_edge[off + i]);
        float4 v0 = *(const float4*)(g_y + (size_t)e0.x * EMB + c4);
        float w0 = __int_as_float(e0.y);
        acc.x += w0 * v0.x; acc.y += w0 * v0.y;
        acc.z += w0 * v0.z; acc.w += w0 * v0.w;
    }

    float* o = out + (size_t)node * EMB + c4;
    float4 cur = *(float4*)o;
    cur.x += acc.x; cur.y += acc.y; cur.z += acc.z; cur.w += acc.w;
    *(float4*)o = cur;
}

// =========== persistent-B HMMA bf16-split GEMM (unchanged from R7) ===========
#define A_KSTR  40
#define A_PLANE (128 * A_KSTR * 2)
#define A_STAGE (2 * A_PLANE)
#define B_KSTR  264
#define B_PLANE (64 * B_KSTR * 2)
#define SM_A    (2 * B_PLANE)
#define SMTOT   (SM_A + 2 * A_STAGE)
#define NSLOT   74

template <int MODE>
__global__ __launch_bounds__(256, 2)
void gcn_gemm_mma(const float* __restrict__ bias, float* __restrict__ dout)
{
    extern __shared__ char smem[];
    const uint32_t sb = smem_u32(smem);

    const int tid  = threadIdx.x;
    const int lane = tid & 31;
    const int wid  = tid >> 5;
    const int wm   = wid >> 1;
    const int wn   = wid & 1;
    const int q    = blockIdx.x & 3;
    const int slot = blockIdx.x >> 2;

    const uint16_t* whi = (MODE == 1) ? g_w1hi : g_w2hi;
    const uint16_t* wlo = (MODE == 1) ? g_w1lo : g_w2lo;

    #pragma unroll
    for (int i = 0; i < 16; i++) {
        int c = i * 256 + tid;
        int plane = c >> 11;
        int rem = c & 2047;
        int row = rem >> 5;
        int col = rem & 31;
        const uint16_t* src = (plane ? wlo : whi) + (size_t)(q * 64 + row) * 256 + col * 8;
        uint32_t dst = sb + plane * B_PLANE + (uint32_t)(row * B_KSTR + col * 8) * 2;
        CP16(dst, src);
    }
    CP_COMMIT();
    cp_wait<0>();
    __syncthreads();

    auto issue = [&](int m0, int kc, int st) {
        const uint16_t *ahs, *als;
        int astr, kb;
        if (MODE == 1) {
            if (kc < 4) { ahs = g_a1hi;  als = g_a1lo; }
            else        { ahs = g_xs_hi; als = g_xs_lo; }
            astr = 128; kb = (kc & 3) * 32;
        } else {
            ahs = g_hhi; als = g_hlo; astr = 256; kb = kc * 32;
        }
        uint32_t base = sb + SM_A + st * A_STAGE;
        #pragma unroll
        for (int i = 0; i < 4; i++) {
            int c = i * 256 + tid;
            int plane = c >> 9;
            int rem = c & 511;
            int row = rem >> 2;
            int col = rem & 3;
            const uint16_t* src = (plane ? als : ahs) + (size_t)(m0 + row) * astr + kb + col * 8;
            uint32_t dst = base + plane * A_PLANE + (uint32_t)(row * A_KSTR + col * 8) * 2;
            CP16(dst, src);
        }
        CP_COMMIT();
    };

    const int rA = (lane & 7) + ((lane >> 3) & 1) * 8;
    const int kA = (lane >> 4) * 8;
    const int rB = (lane & 7) + ((lane >> 4) & 1) * 8;
    const int kB = ((lane >> 3) & 1) * 8;
    const int rr = lane >> 2;
    const int cc = (lane & 3) * 2;

    for (int t = slot; t < NPAD / 128; t += NSLOT) {
        const int m0 = t * 128;

        float acc[2][4][4];
        #pragma unroll
        for (int i = 0; i < 2; i++)
            #pragma unroll
            for (int j = 0; j < 4; j++)
                #pragma unroll
                for (int p = 0; p < 4; p++) acc[i][j][p] = 0.f;

        issue(m0, 0, 0);

        for (int kc = 0; kc < 8; kc++) {
            if (kc + 1 < 8) { issue(m0, kc + 1, (kc + 1) & 1); cp_wait<1>(); }
            else            { cp_wait<0>(); }
            __syncthreads();

            uint32_t uA = sb + SM_A + (kc & 1) * A_STAGE;
            uint32_t uAhi = uA, uAlo = uA + A_PLANE;

            #pragma unroll
            for (int ks = 0; ks < 2; ks++) {
                uint32_t ahi[2][4], alo[2][4];
                #pragma unroll
                for (int mt = 0; mt < 2; mt++) {
                    uint32_t off = ((uint32_t)((wm * 32 + mt * 16 + rA) * A_KSTR + ks * 16 + kA)) * 2;
                    LDSM_X4(ahi[mt][0], ahi[mt][1], ahi[mt][2], ahi[mt][3], uAhi + off);
                    LDSM_X4(alo[mt][0], alo[mt][1], alo[mt][2], alo[mt][3], uAlo + off);
                }
                #pragma unroll
                for (int np = 0; np < 2; np++) {
                    uint32_t boff = ((uint32_t)((wn * 32 + np * 16 + rB) * B_KSTR + kc * 32 + ks * 16 + kB)) * 2;
                    uint32_t bh[4], bl[4];
                    LDSM_X4(bh[0], bh[1], bh[2], bh[3], sb + boff);
                    LDSM_X4(bl[0], bl[1], bl[2], bl[3], sb + B_PLANE + boff);
                    #pragma unroll
                    for (int mt = 0; mt < 2; mt++) {
                        MMA_BF16(acc[mt][np * 2 + 0], ahi[mt], bh[0], bh[1]);
                        MMA_BF16(acc[mt][np * 2 + 0], ahi[mt], bl[0], bl[1]);
                        MMA_BF16(acc[mt][np * 2 + 0], alo[mt], bh[0], bh[1]);
                        MMA_BF16(acc[mt][np * 2 + 1], ahi[mt], bh[2], bh[3]);
                        MMA_BF16(acc[mt][np * 2 + 1], ahi[mt], bl[2], bl[3]);
                        MMA_BF16(acc[mt][np * 2 + 1], alo[mt], bh[2], bh[3]);
                    }
                }
            }
            __syncthreads();
        }

        #pragma unroll
        for (int mt = 0; mt < 2; mt++) {
            #pragma unroll
            for (int j = 0; j < 4; j++) {
                int gm = m0 + wm * 32 + mt * 16 + rr;
                int gN = q * 64 + wn * 32 + j * 8 + cc;
                if (MODE == 1) {
                    float2 bv = *(const float2*)(bias + gN);
                    float v00 = fmaxf(acc[mt][j][0] + bv.x, 0.f);
                    float v01 = fmaxf(acc[mt][j][1] + bv.y, 0.f);
                    float v10 = fmaxf(acc[mt][j][2] + bv.x, 0.f);
                    float v11 = fmaxf(acc[mt][j][3] + bv.y, 0.f);
                    uint16_t h0, l0, h1, l1;
                    split1(v00, h0, l0); split1(v01, h1, l1);
                    *(uint32_t*)&g_hhi[(size_t)gm * 256 + gN] = (uint32_t)h0 | ((uint32_t)h1 << 16);
                    *(uint32_t*)&g_hlo[(size_t)gm * 256 + gN] = (uint32_t)l0 | ((uint32_t)l1 << 16);
                    split1(v10, h0, l0); split1(v11, h1, l1);
                    *(uint32_t*)&g_hhi[(size_t)(gm + 8) * 256 + gN] = (uint32_t)h0 | ((uint32_t)h1 << 16);
                    *(uint32_t*)&g_hlo[(size_t)(gm + 8) * 256 + gN] = (uint32_t)l0 | ((uint32_t)l1 << 16);
                } else if (gN < 128) {
                    *(float2*)(g_y + (size_t)gm * 128 + gN)       = make_float2(acc[mt][j][0], acc[mt][j][1]);
                    *(float2*)(g_y + (size_t)(gm + 8) * 128 + gN) = make_float2(acc[mt][j][2], acc[mt][j][3]);
                } else {
                    int nc = gN - 128;
                    float2 bv = *(const float2*)(bias + nc);
                    if (gm < NN)
                        *(float2*)(dout + (size_t)gm * 128 + nc) =
                            make_float2(acc[mt][j][0] + bv.x, acc[mt][j][1] + bv.y);
                    if (gm + 8 < NN)
                        *(float2*)(dout + (size_t)(gm + 8) * 128 + nc) =
                            make_float2(acc[mt][j][2] + bv.x, acc[mt][j][3] + bv.y);
                }
            }
        }
    }
}

// ---------------- launch ----------------
extern "C" void kernel_launch(void* const* d_in, const int* in_sizes, int n_in,
                              void* d_out, int out_size)
{
    const float* pol   = (const float*)d_in[0];
    const int*   sid   = (const int*)  d_in[1];
    const int*   ei    = (const int*)  d_in[2];
    const float* ew    = (const float*)d_in[3];
    const float* Wp    = (const float*)d_in[4];
    const float* bp    = (const float*)d_in[5];
    const float* semb  = (const float*)d_in[6];
    const float* tick  = (const float*)d_in[7];
    const float* W1rel = (const float*)d_in[8];
    const float* b1    = (const float*)d_in[9];
    const float* W1root= (const float*)d_in[10];
    const float* W2rel = (const float*)d_in[11];
    const float* b2    = (const float*)d_in[12];
    const float* W2root= (const float*)d_in[13];
    float* out = (float*)d_out;

    cudaFuncSetAttribute(gcn_gemm_mma<1>, cudaFuncAttributeMaxDynamicSharedMemorySize, SMTOT);
    cudaFuncSetAttribute(gcn_gemm_mma<2>, cudaFuncAttributeMaxDynamicSharedMemorySize, SMTOT);

    // 0) weight split planes + CSR histogram init
    wconv_kernel<<<512, 256>>>(W1rel, W1root, W2rel, W2root);
    zero_cnt_kernel<<<(NPAD / 4 + 255) / 256, 256>>>();
    // 1) x build (split planes)
    build_x_kernel<<<(NN * 32 + 255) / 256, 256>>>(pol, sid, Wp, bp, semb, tick);
    // 2) CSR build: histogram -> scan -> placement
    hist_kernel<<<(E_EDGES + 255) / 256, 256>>>(ei);
    scan1_kernel<<<NB1, 256>>>();
    scan2_kernel<<<1, 512>>>();
    scan3_kernel<<<NB1, 256>>>();
    place_kernel<<<(E_EDGES + 255) / 256, 256>>>(ei, ew);
    // 3) gather1: agg planes = split( sum w*x )
    gather1_kernel<<<NN * 32 / 256, 256>>>();
    // 4) h = relu([agg1|x] @ [W1;W1root] + b1)  (writes split h planes)
    gcn_gemm_mma<1><<<4 * NSLOT, 256, SMTOT>>>(b1, nullptr);
    // 5) y = h @ W2rel ; out = h @ W2root + b2
    gcn_gemm_mma<2><<<4 * NSLOT, 256, SMTOT>>>(b2, out);
    // 6) gather2: out += sum w*y
    gather2_kernel<<<NN * 32 / 256, 256>>>(out);
}

// round 9
// speedup vs baseline: 3.1024x; 1.1264x over previous
#include <cuda_runtime.h>
#include <cuda_fp16.h>
#include <cstdint>

#define N_POL   100000
#define N_TICK  20000
#define NN      (N_POL + N_TICK)   // 120000
#define NPAD    120064
#define NB1     469
#define E_EDGES 1000000
#define POL_FEAT 7
#define EMB     128
#define HID     256
#define OUTD    128

// ---------------- scratch (static device globals; no allocation) ----------------
__device__ float    g_y[(size_t)NPAD * EMB];      // h @ W2_rel f32 (gather src)
// pre-split fp16 planes
__device__ uint16_t g_xs_hi[(size_t)NPAD * EMB],  g_xs_lo[(size_t)NPAD * EMB];
__device__ uint16_t g_a1hi[(size_t)NPAD * EMB],   g_a1lo[(size_t)NPAD * EMB];
__device__ uint16_t g_hhi[(size_t)NPAD * HID],    g_hlo[(size_t)NPAD * HID];
__device__ uint16_t g_w1hi[256 * 256];            // [n][k] fp16 (hi only)
__device__ uint16_t g_w2hi[256 * 256];
// CSR structures
__device__ int  g_cnt[NPAD];
__device__ int  g_off[NPAD];
__device__ int  g_cur[NPAD];
__device__ int  g_bsum[NB1];
__device__ int  g_boff[NB1];
__device__ int2 g_edge[E_EDGES];    // {src, weight_bits} sorted by dst

// ---------------- helpers ----------------
__device__ __forceinline__ uint32_t smem_u32(const void* p) {
    uint32_t a;
    asm("{ .reg .u64 t; cvta.to.shared.u64 t, %1; cvt.u32.u64 %0, t; }" : "=r"(a) : "l"(p));
    return a;
}
#define LDSM_X4(r0, r1, r2, r3, addr) \
    asm volatile("ldmatrix.sync.aligned.m8n8.x4.shared.b16 {%0,%1,%2,%3}, [%4];" \
        : "=r"(r0), "=r"(r1), "=r"(r2), "=r"(r3) : "r"(addr))
#define MMA_F16(c, a, b0, b1) \
    asm volatile("mma.sync.aligned.m16n8k16.row.col.f32.f16.f16.f32 " \
        "{%0,%1,%2,%3}, {%4,%5,%6,%7}, {%8,%9}, {%0,%1,%2,%3};" \
        : "+f"((c)[0]), "+f"((c)[1]), "+f"((c)[2]), "+f"((c)[3]) \
        : "r"((a)[0]), "r"((a)[1]), "r"((a)[2]), "r"((a)[3]), "r"(b0), "r"(b1))
#define CP16(dst, src) \
    asm volatile("cp.async.cg.shared.global [%0], [%1], 16;" :: "r"(dst), "l"(src))
#define CP_COMMIT() asm volatile("cp.async.commit_group;" ::: "memory")
template <int N> __device__ __forceinline__ void cp_wait() {
    asm volatile("cp.async.wait_group %0;" :: "n"(N) : "memory");
}

__device__ __forceinline__ void split1(float v, uint16_t& h, uint16_t& l) {
    __half bh = __float2half(v);
    float fh = __half2float(bh);
    __half bl = __float2half(v - fh);
    h = *reinterpret_cast<uint16_t*>(&bh);
    l = *reinterpret_cast<uint16_t*>(&bl);
}
__device__ __forceinline__ void split4(float4 v, uint2& hi, uint2& lo) {
    uint16_t h0, l0, h1, l1, h2, l2, h3, l3;
    split1(v.x, h0, l0); split1(v.y, h1, l1);
    split1(v.z, h2, l2); split1(v.w, h3, l3);
    hi = make_uint2((uint32_t)h0 | ((uint32_t)h1 << 16), (uint32_t)h2 | ((uint32_t)h3 << 16));
    lo = make_uint2((uint32_t)l0 | ((uint32_t)l1 << 16), (uint32_t)l2 | ((uint32_t)l3 << 16));
}
__device__ __forceinline__ float4 recon4(uint2 h, uint2 l) {
    float2 a0 = __half22float2(*reinterpret_cast<__half2*>(&h.x));
    float2 b0 = __half22float2(*reinterpret_cast<__half2*>(&l.x));
    float2 a1 = __half22float2(*reinterpret_cast<__half2*>(&h.y));
    float2 b1 = __half22float2(*reinterpret_cast<__half2*>(&l.y));
    return make_float4(a0.x + b0.x, a0.y + b0.y, a1.x + b1.x, a1.y + b1.y);
}

// ---------------- weight conversion (hi plane only) ----------------
__global__ __launch_bounds__(256)
void wconv_kernel(const float* __restrict__ W1rel, const float* __restrict__ W1root,
                  const float* __restrict__ W2rel, const float* __restrict__ W2root)
{
    int idx = blockIdx.x * 256 + threadIdx.x;
    int which = idx >> 16;
    int e = idx & 65535;
    int n = e >> 8, k = e & 255;
    float v;
    if (which == 0) v = (k < 128) ? W1rel[k * 256 + n] : W1root[(k - 128) * 256 + n];
    else            v = (n < 128) ? W2rel[k * 128 + n] : W2root[k * 128 + (n - 128)];
    __half bh = __float2half(v);
    uint16_t h = *reinterpret_cast<uint16_t*>(&bh);
    if (which == 0) g_w1hi[e] = h;
    else            g_w2hi[e] = h;
}

// ---------------- CSR build kernels ----------------
__global__ __launch_bounds__(256)
void zero_cnt_kernel()
{
    int idx = blockIdx.x * 256 + threadIdx.x;
    if (idx < NPAD / 4) ((int4*)g_cnt)[idx] = make_int4(0, 0, 0, 0);
}

__global__ __launch_bounds__(256)
void hist_kernel(const int* __restrict__ ei)
{
    int e = blockIdx.x * 256 + threadIdx.x;
    if (e < E_EDGES) atomicAdd(&g_cnt[ei[E_EDGES + e]], 1);
}

__global__ __launch_bounds__(256)
void scan1_kernel()
{
    __shared__ int s[256];
    int tid = threadIdx.x;
    int idx = blockIdx.x * 256 + tid;
    int v = g_cnt[idx];
    s[tid] = v;
    __syncthreads();
    #pragma unroll
    for (int d = 1; d < 256; d <<= 1) {
        int t = (tid >= d) ? s[tid - d] : 0;
        __syncthreads();
        s[tid] += t;
        __syncthreads();
    }
    g_off[idx] = s[tid] - v;
    if (tid == 255) g_bsum[blockIdx.x] = s[255];
}

__global__ __launch_bounds__(512)
void scan2_kernel()
{
    __shared__ int s[512];
    int tid = threadIdx.x;
    int v = (tid < NB1) ? g_bsum[tid] : 0;
    s[tid] = v;
    __syncthreads();
    #pragma unroll
    for (int d = 1; d < 512; d <<= 1) {
        int t = (tid >= d) ? s[tid - d] : 0;
        __syncthreads();
        s[tid] += t;
        __syncthreads();
    }
    if (tid < NB1) g_boff[tid] = s[tid] - v;
}

__global__ __launch_bounds__(256)
void scan3_kernel()
{
    int idx = blockIdx.x * 256 + threadIdx.x;
    int o = g_off[idx] + g_boff[blockIdx.x];
    g_off[idx] = o;
    g_cur[idx] = o;
}

__global__ __launch_bounds__(256)
void place_kernel(const int* __restrict__ ei, const float* __restrict__ ew)
{
    int e = blockIdx.x * 256 + threadIdx.x;
    if (e >= E_EDGES) return;
    int s = ei[e];
    int d = ei[E_EDGES + e];
    float w = ew[e];
    int pos = atomicAdd(&g_cur[d], 1);
    g_edge[pos] = make_int2(s, __float_as_int(w));
}

// ---------------- build x split planes ----------------
__global__ __launch_bounds__(256)
void build_x_kernel(const float* __restrict__ pol, const int* __restrict__ sid,
                    const float* __restrict__ Wp, const float* __restrict__ bp,
                    const float* __restrict__ semb, const float* __restrict__ tick)
{
    int t = blockIdx.x * blockDim.x + threadIdx.x;
    int node = t >> 5;
    int c4 = (t & 31) * 4;
    if (node >= NN) return;

    float4 r;
    if (node < N_POL) {
        float4 acc = *(const float4*)(bp + c4);
        #pragma unroll
        for (int k = 0; k < POL_FEAT; k++) {
            float f = __ldg(pol + node * POL_FEAT + k);
            float4 w = *(const float4*)(Wp + k * EMB + c4);
            acc.x += f * w.x; acc.y += f * w.y; acc.z += f * w.z; acc.w += f * w.w;
        }
        int s = sid[node];
        float4 se = *(const float4*)(semb + (size_t)s * EMB + c4);
        r.x = fmaxf(acc.x, 0.f) + se.x;
        r.y = fmaxf(acc.y, 0.f) + se.y;
        r.z = fmaxf(acc.z, 0.f) + se.z;
        r.w = fmaxf(acc.w, 0.f) + se.w;
    } else {
        r = *(const float4*)(tick + (size_t)(node - N_POL) * EMB + c4);
    }
    uint2 hi, lo;
    split4(r, hi, lo);
    *(uint2*)&g_xs_hi[(size_t)node * EMB + c4] = hi;
    *(uint2*)&g_xs_lo[(size_t)node * EMB + c4] = lo;
}

// ---------------- gather1: agg1 planes = split( sum_e w * x[src] ) ----------------
__global__ __launch_bounds__(256)
void gather1_kernel()
{
    int t = blockIdx.x * blockDim.x + threadIdx.x;
    int node = t >> 5;
    int c4 = (t & 31) * 4;
    if (node >= NN) return;

    int cnt = __ldg(&g_cnt[node]);
    int off = __ldg(&g_off[node]);

    float4 acc = make_float4(0.f, 0.f, 0.f, 0.f);
    int i = 0;
    for (; i + 1 < cnt; i += 2) {
        int2 e0 = __ldg(&g_edge[off + i]);
        int2 e1 = __ldg(&g_edge[off + i + 1]);
        uint2 h0 = *(const uint2*)&g_xs_hi[(size_t)e0.x * EMB + c4];
        uint2 l0 = *(const uint2*)&g_xs_lo[(size_t)e0.x * EMB + c4];
        uint2 h1 = *(const uint2*)&g_xs_hi[(size_t)e1.x * EMB + c4];
        uint2 l1 = *(const uint2*)&g_xs_lo[(size_t)e1.x * EMB + c4];
        float w0 = __int_as_float(e0.y);
        float w1 = __int_as_float(e1.y);
        float4 v0 = recon4(h0, l0);
        float4 v1 = recon4(h1, l1);
        acc.x += w0 * v0.x + w1 * v1.x;
        acc.y += w0 * v0.y + w1 * v1.y;
        acc.z += w0 * v0.z + w1 * v1.z;
        acc.w += w0 * v0.w + w1 * v1.w;
    }
    if (i < cnt) {
        int2 e0 = __ldg(&g_edge[off + i]);
        uint2 h0 = *(const uint2*)&g_xs_hi[(size_t)e0.x * EMB + c4];
        uint2 l0 = *(const uint2*)&g_xs_lo[(size_t)e0.x * EMB + c4];
        float w0 = __int_as_float(e0.y);
        float4 v0 = recon4(h0, l0);
        acc.x += w0 * v0.x; acc.y += w0 * v0.y;
        acc.z += w0 * v0.z; acc.w += w0 * v0.w;
    }

    uint2 hi, lo;
    split4(acc, hi, lo);
    *(uint2*)&g_a1hi[(size_t)node * EMB + c4] = hi;
    *(uint2*)&g_a1lo[(size_t)node * EMB + c4] = lo;
}

// ---------------- gather2: out += sum_e w * y[src] ----------------
__global__ __launch_bounds__(256)
void gather2_kernel(float* __restrict__ out)
{
    int t = blockIdx.x * blockDim.x + threadIdx.x;
    int node = t >> 5;
    int c4 = (t & 31) * 4;
    if (node >= NN) return;

    int cnt = __ldg(&g_cnt[node]);
    if (cnt == 0) return;
    int off = __ldg(&g_off[node]);

    float4 acc = make_float4(0.f, 0.f, 0.f, 0.f);
    int i = 0;
    for (; i + 1 < cnt; i += 2) {
        int2 e0 = __ldg(&g_edge[off + i]);
        int2 e1 = __ldg(&g_edge[off + i + 1]);
        float4 v0 = *(const float4*)(g_y + (size_t)e0.x * EMB + c4);
        float4 v1 = *(const float4*)(g_y + (size_t)e1.x * EMB + c4);
        float w0 = __int_as_float(e0.y);
        float w1 = __int_as_float(e1.y);
        acc.x += w0 * v0.x + w1 * v1.x;
        acc.y += w0 * v0.y + w1 * v1.y;
        acc.z += w0 * v0.z + w1 * v1.z;
        acc.w += w0 * v0.w + w1 * v1.w;
    }
    if (i < cnt) {
        int2 e0 = __ldg(&g_edge[off + i]);
        float4 v0 = *(const float4*)(g_y + (size_t)e0.x * EMB + c4);
        float w0 = __int_as_float(e0.y);
        acc.x += w0 * v0.x; acc.y += w0 * v0.y;
        acc.z += w0 * v0.z; acc.w += w0 * v0.w;
    }

    float* o = out + (size_t)node * EMB + c4;
    float4 cur = *(float4*)o;
    cur.x += acc.x; cur.y += acc.y; cur.z += acc.z; cur.w += acc.w;
    *(float4*)o = cur;
}

// =========== persistent-B HMMA fp16-split GEMM (2 products: AhiBhi + AloBhi) ===========
#define A_KSTR  40
#define A_PLANE (128 * A_KSTR * 2)        // 10240
#define A_STAGE (2 * A_PLANE)             // 20480
#define B_KSTR  264
#define B_PLANE (64 * B_KSTR * 2)         // 33792 (hi plane only)
#define SM_A    (B_PLANE)
#define SMTOT   (SM_A + 2 * A_STAGE)      // 74752
#define NSLOT   111                       // 444 CTAs / 4 quarters (3 per SM)

template <int MODE>
__global__ __launch_bounds__(256, 3)
void gcn_gemm_mma(const float* __restrict__ bias, float* __restrict__ dout)
{
    extern __shared__ char smem[];
    const uint32_t sb = smem_u32(smem);

    const int tid  = threadIdx.x;
    const int lane = tid & 31;
    const int wid  = tid >> 5;
    const int wm   = wid >> 1;
    const int wn   = wid & 1;
    const int q    = blockIdx.x & 3;
    const int slot = blockIdx.x >> 2;

    const uint16_t* whi = (MODE == 1) ? g_w1hi : g_w2hi;

    // ---- load B quarter once: [64 n][256 k] hi plane
    #pragma unroll
    for (int i = 0; i < 8; i++) {
        int c = i * 256 + tid;            // 0..2047
        int row = c >> 5;                 // 0..63
        int col = c & 31;                 // 16B chunk (8 fp16)
        const uint16_t* src = whi + (size_t)(q * 64 + row) * 256 + col * 8;
        uint32_t dst = sb + (uint32_t)(row * B_KSTR + col * 8) * 2;
        CP16(dst, src);
    }
    CP_COMMIT();
    cp_wait<0>();
    __syncthreads();

    auto issue = [&](int m0, int kc, int st) {
        const uint16_t *ahs, *als;
        int astr, kb;
        if (MODE == 1) {
            if (kc < 4) { ahs = g_a1hi;  als = g_a1lo; }
            else        { ahs = g_xs_hi; als = g_xs_lo; }
            astr = 128; kb = (kc & 3) * 32;
        } else {
            ahs = g_hhi; als = g_hlo; astr = 256; kb = kc * 32;
        }
        uint32_t base = sb + SM_A + st * A_STAGE;
        #pragma unroll
        for (int i = 0; i < 4; i++) {
            int c = i * 256 + tid;          // 0..1023
            int plane = c >> 9;
            int rem = c & 511;
            int row = rem >> 2;             // 0..127
            int col = rem & 3;
            const uint16_t* src = (plane ? als : ahs) + (size_t)(m0 + row) * astr + kb + col * 8;
            uint32_t dst = base + plane * A_PLANE + (uint32_t)(row * A_KSTR + col * 8) * 2;
            CP16(dst, src);
        }
        CP_COMMIT();
    };

    const int rA = (lane & 7) + ((lane >> 3) & 1) * 8;
    const int kA = (lane >> 4) * 8;
    const int rB = (lane & 7) + ((lane >> 4) & 1) * 8;
    const int kB = ((lane >> 3) & 1) * 8;
    const int rr = lane >> 2;
    const int cc = (lane & 3) * 2;

    for (int t = slot; t < NPAD / 128; t += NSLOT) {
        const int m0 = t * 128;

        float acc[2][4][4];
        #pragma unroll
        for (int i = 0; i < 2; i++)
            #pragma unroll
            for (int j = 0; j < 4; j++)
                #pragma unroll
                for (int p = 0; p < 4; p++) acc[i][j][p] = 0.f;

        issue(m0, 0, 0);

        for (int kc = 0; kc < 8; kc++) {
            if (kc + 1 < 8) { issue(m0, kc + 1, (kc + 1) & 1); cp_wait<1>(); }
            else            { cp_wait<0>(); }
            __syncthreads();

            uint32_t uA = sb + SM_A + (kc & 1) * A_STAGE;
            uint32_t uAhi = uA, uAlo = uA + A_PLANE;

            #pragma unroll
            for (int ks = 0; ks < 2; ks++) {
                uint32_t ahi[2][4], alo[2][4];
                #pragma unroll
                for (int mt = 0; mt < 2; mt++) {
                    uint32_t off = ((uint32_t)((wm * 32 + mt * 16 + rA) * A_KSTR + ks * 16 + kA)) * 2;
                    LDSM_X4(ahi[mt][0], ahi[mt][1], ahi[mt][2], ahi[mt][3], uAhi + off);
                    LDSM_X4(alo[mt][0], alo[mt][1], alo[mt][2], alo[mt][3], uAlo + off);
                }
                #pragma unroll
                for (int np = 0; np < 2; np++) {
                    uint32_t boff = ((uint32_t)((wn * 32 + np * 16 + rB) * B_KSTR + kc * 32 + ks * 16 + kB)) * 2;
                    uint32_t bh[4];
                    LDSM_X4(bh[0], bh[1], bh[2], bh[3], sb + boff);
                    #pragma unroll
                    for (int mt = 0; mt < 2; mt++) {
                        MMA_F16(acc[mt][np * 2 + 0], ahi[mt], bh[0], bh[1]);
                        MMA_F16(acc[mt][np * 2 + 0], alo[mt], bh[0], bh[1]);
                        MMA_F16(acc[mt][np * 2 + 1], ahi[mt], bh[2], bh[3]);
                        MMA_F16(acc[mt][np * 2 + 1], alo[mt], bh[2], bh[3]);
                    }
                }
            }
            __syncthreads();
        }

        #pragma unroll
        for (int mt = 0; mt < 2; mt++) {
            #pragma unroll
            for (int j = 0; j < 4; j++) {
                int gm = m0 + wm * 32 + mt * 16 + rr;
                int gN = q * 64 + wn * 32 + j * 8 + cc;
                if (MODE == 1) {
                    float2 bv = *(const float2*)(bias + gN);
                    float v00 = fmaxf(acc[mt][j][0] + bv.x, 0.f);
                    float v01 = fmaxf(acc[mt][j][1] + bv.y, 0.f);
                    float v10 = fmaxf(acc[mt][j][2] + bv.x, 0.f);
                    float v11 = fmaxf(acc[mt][j][3] + bv.y, 0.f);
                    uint16_t h0, l0, h1, l1;
                    split1(v00, h0, l0); split1(v01, h1, l1);
                    *(uint32_t*)&g_hhi[(size_t)gm * 256 + gN] = (uint32_t)h0 | ((uint32_t)h1 << 16);
                    *(uint32_t*)&g_hlo[(size_t)gm * 256 + gN] = (uint32_t)l0 | ((uint32_t)l1 << 16);
                    split1(v10, h0, l0); split1(v11, h1, l1);
                    *(uint32_t*)&g_hhi[(size_t)(gm + 8) * 256 + gN] = (uint32_t)h0 | ((uint32_t)h1 << 16);
                    *(uint32_t*)&g_hlo[(size_t)(gm + 8) * 256 + gN] = (uint32_t)l0 | ((uint32_t)l1 << 16);
                } else if (gN < 128) {
                    *(float2*)(g_y + (size_t)gm * 128 + gN)       = make_float2(acc[mt][j][0], acc[mt][j][1]);
                    *(float2*)(g_y + (size_t)(gm + 8) * 128 + gN) = make_float2(acc[mt][j][2], acc[mt][j][3]);
                } else {
                    int nc = gN - 128;
                    float2 bv = *(const float2*)(bias + nc);
                    if (gm < NN)
                        *(float2*)(dout + (size_t)gm * 128 + nc) =
                            make_float2(acc[mt][j][0] + bv.x, acc[mt][j][1] + bv.y);
                    if (gm + 8 < NN)
                        *(float2*)(dout + (size_t)(gm + 8) * 128 + nc) =
                            make_float2(acc[mt][j][2] + bv.x, acc[mt][j][3] + bv.y);
                }
            }
        }
    }
}

// ---------------- launch ----------------
extern "C" void kernel_launch(void* const* d_in, const int* in_sizes, int n_in,
                              void* d_out, int out_size)
{
    const float* pol   = (const float*)d_in[0];
    const int*   sid   = (const int*)  d_in[1];
    const int*   ei    = (const int*)  d_in[2];
    const float* ew    = (const float*)d_in[3];
    const float* Wp    = (const float*)d_in[4];
    const float* bp    = (const float*)d_in[5];
    const float* semb  = (const float*)d_in[6];
    const float* tick  = (const float*)d_in[7];
    const float* W1rel = (const float*)d_in[8];
    const float* b1    = (const float*)d_in[9];
    const float* W1root= (const float*)d_in[10];
    const float* W2rel = (const float*)d_in[11];
    const float* b2    = (const float*)d_in[12];
    const float* W2root= (const float*)d_in[13];
    float* out = (float*)d_out;

    cudaFuncSetAttribute(gcn_gemm_mma<1>, cudaFuncAttributeMaxDynamicSharedMemorySize, SMTOT);
    cudaFuncSetAttribute(gcn_gemm_mma<2>, cudaFuncAttributeMaxDynamicSharedMemorySize, SMTOT);

    // 0) weight hi planes + CSR init
    wconv_kernel<<<512, 256>>>(W1rel, W1root, W2rel, W2root);
    zero_cnt_kernel<<<(NPAD / 4 + 255) / 256, 256>>>();
    // 1) x build (split planes)
    build_x_kernel<<<(NN * 32 + 255) / 256, 256>>>(pol, sid, Wp, bp, semb, tick);
    // 2) CSR build
    hist_kernel<<<(E_EDGES + 255) / 256, 256>>>(ei);
    scan1_kernel<<<NB1, 256>>>();
    scan2_kernel<<<1, 512>>>();
    scan3_kernel<<<NB1, 256>>>();
    place_kernel<<<(E_EDGES + 255) / 256, 256>>>(ei, ew);
    // 3) gather1
    gather1_kernel<<<NN * 32 / 256, 256>>>();
    // 4) GEMM1
    gcn_gemm_mma<1><<<4 * NSLOT, 256, SMTOT>>>(b1, nullptr);
    // 5) GEMM2
    gcn_gemm_mma<2><<<4 * NSLOT, 256, SMTOT>>>(b2, out);
    // 6) gather2
    gather2_kernel<<<NN * 32 / 256, 256>>>(out);
}

// round 10
// speedup vs baseline: 3.5924x; 1.1579x over previous
#include <cuda_runtime.h>
#include <cuda_fp16.h>
#include <cstdint>

#define N_POL   100000
#define N_TICK  20000
#define NN      (N_POL + N_TICK)   // 120000
#define NPAD    120064
#define NB1     469
#define E_EDGES 1000000
#define POL_FEAT 7
#define EMB     128
#define HID     256
#define OUTD    128

// ---------------- scratch (static device globals; no allocation) ----------------
__device__ float    g_y[(size_t)NPAD * EMB];      // h @ W2_rel f32 (gather src)
// pre-split fp16 planes
__device__ uint16_t g_xs_hi[(size_t)NPAD * EMB],  g_xs_lo[(size_t)NPAD * EMB];
__device__ uint16_t g_a1hi[(size_t)NPAD * EMB],   g_a1lo[(size_t)NPAD * EMB];
__device__ uint16_t g_hhi[(size_t)NPAD * HID];    // h fp16 (hi only)
__device__ uint16_t g_w1hi[256 * 256];            // [n][k] fp16 (hi only)
__device__ uint16_t g_w2hi[256 * 256];
// CSR structures
__device__ int  g_cnt[NPAD];
__device__ int  g_off[NPAD];
__device__ int  g_cur[NPAD];
__device__ int  g_bsum[NB1];
__device__ int  g_boff[NB1];
__device__ int2 g_edge[E_EDGES];    // {src, weight_bits} sorted by dst

// ---------------- helpers ----------------
__device__ __forceinline__ uint32_t smem_u32(const void* p) {
    uint32_t a;
    asm("{ .reg .u64 t; cvta.to.shared.u64 t, %1; cvt.u32.u64 %0, t; }" : "=r"(a) : "l"(p));
    return a;
}
#define LDSM_X4(r0, r1, r2, r3, addr) \
    asm volatile("ldmatrix.sync.aligned.m8n8.x4.shared.b16 {%0,%1,%2,%3}, [%4];" \
        : "=r"(r0), "=r"(r1), "=r"(r2), "=r"(r3) : "r"(addr))
#define MMA_F16(c, a, b0, b1) \
    asm volatile("mma.sync.aligned.m16n8k16.row.col.f32.f16.f16.f32 " \
        "{%0,%1,%2,%3}, {%4,%5,%6,%7}, {%8,%9}, {%0,%1,%2,%3};" \
        : "+f"((c)[0]), "+f"((c)[1]), "+f"((c)[2]), "+f"((c)[3]) \
        : "r"((a)[0]), "r"((a)[1]), "r"((a)[2]), "r"((a)[3]), "r"(b0), "r"(b1))
#define CP16(dst, src) \
    asm volatile("cp.async.cg.shared.global [%0], [%1], 16;" :: "r"(dst), "l"(src))
#define CP_COMMIT() asm volatile("cp.async.commit_group;" ::: "memory")
template <int N> __device__ __forceinline__ void cp_wait() {
    asm volatile("cp.async.wait_group %0;" :: "n"(N) : "memory");
}

__device__ __forceinline__ void split1(float v, uint16_t& h, uint16_t& l) {
    __half bh = __float2half(v);
    float fh = __half2float(bh);
    __half bl = __float2half(v - fh);
    h = *reinterpret_cast<uint16_t*>(&bh);
    l = *reinterpret_cast<uint16_t*>(&bl);
}
__device__ __forceinline__ void split4(float4 v, uint2& hi, uint2& lo) {
    uint16_t h0, l0, h1, l1, h2, l2, h3, l3;
    split1(v.x, h0, l0); split1(v.y, h1, l1);
    split1(v.z, h2, l2); split1(v.w, h3, l3);
    hi = make_uint2((uint32_t)h0 | ((uint32_t)h1 << 16), (uint32_t)h2 | ((uint32_t)h3 << 16));
    lo = make_uint2((uint32_t)l0 | ((uint32_t)l1 << 16), (uint32_t)l2 | ((uint32_t)l3 << 16));
}
__device__ __forceinline__ float4 recon4(uint2 h, uint2 l) {
    float2 a0 = __half22float2(*reinterpret_cast<__half2*>(&h.x));
    float2 b0 = __half22float2(*reinterpret_cast<__half2*>(&l.x));
    float2 a1 = __half22float2(*reinterpret_cast<__half2*>(&h.y));
    float2 b1 = __half22float2(*reinterpret_cast<__half2*>(&l.y));
    return make_float4(a0.x + b0.x, a0.y + b0.y, a1.x + b1.x, a1.y + b1.y);
}
__device__ __forceinline__ uint32_t pack_h2(float a, float b) {
    __half2 t = __floats2half2_rn(a, b);
    return *reinterpret_cast<uint32_t*>(&t);
}

// ---------------- weight conversion (hi plane only) + zero g_cnt ----------------
__global__ __launch_bounds__(256)
void wconv_kernel(const float* __restrict__ W1rel, const float* __restrict__ W1root,
                  const float* __restrict__ W2rel, const float* __restrict__ W2root)
{
    int idx = blockIdx.x * 256 + threadIdx.x;
    if (idx < NPAD / 4) ((int4*)g_cnt)[idx] = make_int4(0, 0, 0, 0);
    int which = idx >> 16;
    int e = idx & 65535;
    int n = e >> 8, k = e & 255;
    float v;
    if (which == 0) v = (k < 128) ? W1rel[k * 256 + n] : W1root[(k - 128) * 256 + n];
    else            v = (n < 128) ? W2rel[k * 128 + n] : W2root[k * 128 + (n - 128)];
    __half bh = __float2half(v);
    uint16_t h = *reinterpret_cast<uint16_t*>(&bh);
    if (which == 0) g_w1hi[e] = h;
    else            g_w2hi[e] = h;
}

// ---------------- CSR build kernels ----------------
__global__ __launch_bounds__(256)
void hist_kernel(const int* __restrict__ ei)
{
    int e = blockIdx.x * 256 + threadIdx.x;
    if (e < E_EDGES) atomicAdd(&g_cnt[ei[E_EDGES + e]], 1);
}

__global__ __launch_bounds__(256)
void scan1_kernel()
{
    __shared__ int s[256];
    int tid = threadIdx.x;
    int idx = blockIdx.x * 256 + tid;
    int v = g_cnt[idx];
    s[tid] = v;
    __syncthreads();
    #pragma unroll
    for (int d = 1; d < 256; d <<= 1) {
        int t = (tid >= d) ? s[tid - d] : 0;
        __syncthreads();
        s[tid] += t;
        __syncthreads();
    }
    g_off[idx] = s[tid] - v;
    if (tid == 255) g_bsum[blockIdx.x] = s[255];
}

__global__ __launch_bounds__(512)
void scan2_kernel()
{
    __shared__ int s[512];
    int tid = threadIdx.x;
    int v = (tid < NB1) ? g_bsum[tid] : 0;
    s[tid] = v;
    __syncthreads();
    #pragma unroll
    for (int d = 1; d < 512; d <<= 1) {
        int t = (tid >= d) ? s[tid - d] : 0;
        __syncthreads();
        s[tid] += t;
        __syncthreads();
    }
    if (tid < NB1) g_boff[tid] = s[tid] - v;
}

__global__ __launch_bounds__(256)
void scan3_kernel()
{
    int idx = blockIdx.x * 256 + threadIdx.x;
    int o = g_off[idx] + g_boff[blockIdx.x];
    g_off[idx] = o;
    g_cur[idx] = o;
}

__global__ __launch_bounds__(256)
void place_kernel(const int* __restrict__ ei, const float* __restrict__ ew)
{
    int e = blockIdx.x * 256 + threadIdx.x;
    if (e >= E_EDGES) return;
    int s = ei[e];
    int d = ei[E_EDGES + e];
    float w = ew[e];
    int pos = atomicAdd(&g_cur[d], 1);
    g_edge[pos] = make_int2(s, __float_as_int(w));
}

// ---------------- build x split planes ----------------
__global__ __launch_bounds__(256)
void build_x_kernel(const float* __restrict__ pol, const int* __restrict__ sid,
                    const float* __restrict__ Wp, const float* __restrict__ bp,
                    const float* __restrict__ semb, const float* __restrict__ tick)
{
    int t = blockIdx.x * blockDim.x + threadIdx.x;
    int node = t >> 5;
    int c4 = (t & 31) * 4;
    if (node >= NN) return;

    float4 r;
    if (node < N_POL) {
        float4 acc = *(const float4*)(bp + c4);
        #pragma unroll
        for (int k = 0; k < POL_FEAT; k++) {
            float f = __ldg(pol + node * POL_FEAT + k);
            float4 w = *(const float4*)(Wp + k * EMB + c4);
            acc.x += f * w.x; acc.y += f * w.y; acc.z += f * w.z; acc.w += f * w.w;
        }
        int s = sid[node];
        float4 se = *(const float4*)(semb + (size_t)s * EMB + c4);
        r.x = fmaxf(acc.x, 0.f) + se.x;
        r.y = fmaxf(acc.y, 0.f) + se.y;
        r.z = fmaxf(acc.z, 0.f) + se.z;
        r.w = fmaxf(acc.w, 0.f) + se.w;
    } else {
        r = *(const float4*)(tick + (size_t)(node - N_POL) * EMB + c4);
    }
    uint2 hi, lo;
    split4(r, hi, lo);
    *(uint2*)&g_xs_hi[(size_t)node * EMB + c4] = hi;
    *(uint2*)&g_xs_lo[(size_t)node * EMB + c4] = lo;
}

// ---------------- gather1: agg1 planes = split( sum_e w * x[src] ) ----------------
__global__ __launch_bounds__(256)
void gather1_kernel()
{
    int t = blockIdx.x * blockDim.x + threadIdx.x;
    int node = t >> 5;
    int c4 = (t & 31) * 4;
    if (node >= NN) return;

    int cnt = __ldg(&g_cnt[node]);
    int off = __ldg(&g_off[node]);

    float4 acc = make_float4(0.f, 0.f, 0.f, 0.f);
    int i = 0;
    for (; i + 1 < cnt; i += 2) {
        int2 e0 = __ldg(&g_edge[off + i]);
        int2 e1 = __ldg(&g_edge[off + i + 1]);
        uint2 h0 = *(const uint2*)&g_xs_hi[(size_t)e0.x * EMB + c4];
        uint2 l0 = *(const uint2*)&g_xs_lo[(size_t)e0.x * EMB + c4];
        uint2 h1 = *(const uint2*)&g_xs_hi[(size_t)e1.x * EMB + c4];
        uint2 l1 = *(const uint2*)&g_xs_lo[(size_t)e1.x * EMB + c4];
        float w0 = __int_as_float(e0.y);
        float w1 = __int_as_float(e1.y);
        float4 v0 = recon4(h0, l0);
        float4 v1 = recon4(h1, l1);
        acc.x += w0 * v0.x + w1 * v1.x;
        acc.y += w0 * v0.y + w1 * v1.y;
        acc.z += w0 * v0.z + w1 * v1.z;
        acc.w += w0 * v0.w + w1 * v1.w;
    }
    if (i < cnt) {
        int2 e0 = __ldg(&g_edge[off + i]);
        uint2 h0 = *(const uint2*)&g_xs_hi[(size_t)e0.x * EMB + c4];
        uint2 l0 = *(const uint2*)&g_xs_lo[(size_t)e0.x * EMB + c4];
        float w0 = __int_as_float(e0.y);
        float4 v0 = recon4(h0, l0);
        acc.x += w0 * v0.x; acc.y += w0 * v0.y;
        acc.z += w0 * v0.z; acc.w += w0 * v0.w;
    }

    uint2 hi, lo;
    split4(acc, hi, lo);
    *(uint2*)&g_a1hi[(size_t)node * EMB + c4] = hi;
    *(uint2*)&g_a1lo[(size_t)node * EMB + c4] = lo;
}

// ---------------- gather2: out += sum_e w * y[src] ----------------
__global__ __launch_bounds__(256)
void gather2_kernel(float* __restrict__ out)
{
    int t = blockIdx.x * blockDim.x + threadIdx.x;
    int node = t >> 5;
    int c4 = (t & 31) * 4;
    if (node >= NN) return;

    int cnt = __ldg(&g_cnt[node]);
    if (cnt == 0) return;
    int off = __ldg(&g_off[node]);

    float4 acc = make_float4(0.f, 0.f, 0.f, 0.f);
    int i = 0;
    for (; i + 1 < cnt; i += 2) {
        int2 e0 = __ldg(&g_edge[off + i]);
        int2 e1 = __ldg(&g_edge[off + i + 1]);
        float4 v0 = *(const float4*)(g_y + (size_t)e0.x * EMB + c4);
        float4 v1 = *(const float4*)(g_y + (size_t)e1.x * EMB + c4);
        float w0 = __int_as_float(e0.y);
        float w1 = __int_as_float(e1.y);
        acc.x += w0 * v0.x + w1 * v1.x;
        acc.y += w0 * v0.y + w1 * v1.y;
        acc.z += w0 * v0.z + w1 * v1.z;
        acc.w += w0 * v0.w + w1 * v1.w;
    }
    if (i < cnt) {
        int2 e0 = __ldg(&g_edge[off + i]);
        float4 v0 = *(const float4*)(g_y + (size_t)e0.x * EMB + c4);
        float w0 = __int_as_float(e0.y);
        acc.x += w0 * v0.x; acc.y += w0 * v0.y;
        acc.z += w0 * v0.z; acc.w += w0 * v0.w;
    }

    float* o = out + (size_t)node * EMB + c4;
    float4 cur = *(float4*)o;
    cur.x += acc.x; cur.y += acc.y; cur.z += acc.z; cur.w += acc.w;
    *(float4*)o = cur;
}

// =========== persistent-B HMMA fp16 GEMM ===========
// MODE 1: A = [a1|x] hi+lo planes (2 products), writes g_hhi (hi only)
// MODE 2: A = h hi plane (1 product), writes y | out
#define A_KSTR  40
#define A_PLANE (128 * A_KSTR * 2)        // 10240
#define B_KSTR  264
#define B_PLANE (64 * B_KSTR * 2)         // 33792
#define SM_A    (B_PLANE)
#define SMTOT1  (SM_A + 2 * 2 * A_PLANE)  // 74752
#define SMTOT2  (SM_A + 2 * 1 * A_PLANE)  // 54272
#define NSLOT   111                       // 444 CTAs / 4 quarters (3 per SM)

template <int MODE>
__global__ __launch_bounds__(256, 3)
void gcn_gemm_mma(const float* __restrict__ bias, float* __restrict__ dout)
{
    extern __shared__ char smem[];
    const uint32_t sb = smem_u32(smem);
    constexpr int APL = (MODE == 1) ? 2 : 1;           // A planes
    constexpr int A_STG = APL * A_PLANE;

    const int tid  = threadIdx.x;
    const int lane = tid & 31;
    const int wid  = tid >> 5;
    const int wm   = wid >> 1;
    const int wn   = wid & 1;
    const int q    = blockIdx.x & 3;
    const int slot = blockIdx.x >> 2;

    const uint16_t* whi = (MODE == 1) ? g_w1hi : g_w2hi;

    // ---- load B quarter once: [64 n][256 k] hi plane
    #pragma unroll
    for (int i = 0; i < 8; i++) {
        int c = i * 256 + tid;
        int row = c >> 5;
        int col = c & 31;
        const uint16_t* src = whi + (size_t)(q * 64 + row) * 256 + col * 8;
        uint32_t dst = sb + (uint32_t)(row * B_KSTR + col * 8) * 2;
        CP16(dst, src);
    }
    CP_COMMIT();
    cp_wait<0>();
    __syncthreads();

    auto issue = [&](int m0, int kc, int st) {
        const uint16_t *ahs, *als;
        int astr, kb;
        if (MODE == 1) {
            if (kc < 4) { ahs = g_a1hi;  als = g_a1lo; }
            else        { ahs = g_xs_hi; als = g_xs_lo; }
            astr = 128; kb = (kc & 3) * 32;
        } else {
            ahs = g_hhi; als = nullptr; astr = 256; kb = kc * 32;
        }
        uint32_t base = sb + SM_A + st * A_STG;
        #pragma unroll
        for (int i = 0; i < 2 * APL; i++) {
            int c = i * 256 + tid;          // 0..(512*APL-1)
            int plane = c >> 9;
            int rem = c & 511;
            int row = rem >> 2;
            int col = rem & 3;
            const uint16_t* src = (plane ? als : ahs) + (size_t)(m0 + row) * astr + kb + col * 8;
            uint32_t dst = base + plane * A_PLANE + (uint32_t)(row * A_KSTR + col * 8) * 2;
            CP16(dst, src);
        }
        CP_COMMIT();
    };

    const int rA = (lane & 7) + ((lane >> 3) & 1) * 8;
    const int kA = (lane >> 4) * 8;
    const int rB = (lane & 7) + ((lane >> 4) & 1) * 8;
    const int kB = ((lane >> 3) & 1) * 8;
    const int rr = lane >> 2;
    const int cc = (lane & 3) * 2;

    for (int t = slot; t < NPAD / 128; t += NSLOT) {
        const int m0 = t * 128;

        float acc[2][4][4];
        #pragma unroll
        for (int i = 0; i < 2; i++)
            #pragma unroll
            for (int j = 0; j < 4; j++)
                #pragma unroll
                for (int p = 0; p < 4; p++) acc[i][j][p] = 0.f;

        issue(m0, 0, 0);

        for (int kc = 0; kc < 8; kc++) {
            cp_wait<0>();              // stage kc data landed
            __syncthreads();           // publish + protect stage (kc+1)&1 reuse
            if (kc + 1 < 8) issue(m0, kc + 1, (kc + 1) & 1);

            uint32_t uA = sb + SM_A + (kc & 1) * A_STG;
            uint32_t uAhi = uA, uAlo = uA + A_PLANE;

            #pragma unroll
            for (int ks = 0; ks < 2; ks++) {
                uint32_t ahi[2][4], alo[2][4];
                #pragma unroll
                for (int mt = 0; mt < 2; mt++) {
                    uint32_t off = ((uint32_t)((wm * 32 + mt * 16 + rA) * A_KSTR + ks * 16 + kA)) * 2;
                    LDSM_X4(ahi[mt][0], ahi[mt][1], ahi[mt][2], ahi[mt][3], uAhi + off);
                    if (MODE == 1)
                        LDSM_X4(alo[mt][0], alo[mt][1], alo[mt][2], alo[mt][3], uAlo + off);
                }
                #pragma unroll
                for (int np = 0; np < 2; np++) {
                    uint32_t boff = ((uint32_t)((wn * 32 + np * 16 + rB) * B_KSTR + kc * 32 + ks * 16 + kB)) * 2;
                    uint32_t bh[4];
                    LDSM_X4(bh[0], bh[1], bh[2], bh[3], sb + boff);
                    #pragma unroll
                    for (int mt = 0; mt < 2; mt++) {
                        MMA_F16(acc[mt][np * 2 + 0], ahi[mt], bh[0], bh[1]);
                        MMA_F16(acc[mt][np * 2 + 1], ahi[mt], bh[2], bh[3]);
                        if (MODE == 1) {
                            MMA_F16(acc[mt][np * 2 + 0], alo[mt], bh[0], bh[1]);
                            MMA_F16(acc[mt][np * 2 + 1], alo[mt], bh[2], bh[3]);
                        }
                    }
                }
            }
            __syncthreads();           // all reads of stage kc done before its reuse at kc+2
        }

        #pragma unroll
        for (int mt = 0; mt < 2; mt++) {
            #pragma unroll
            for (int j = 0; j < 4; j++) {
                int gm = m0 + wm * 32 + mt * 16 + rr;
                int gN = q * 64 + wn * 32 + j * 8 + cc;
                if (MODE == 1) {
                    float2 bv = *(const float2*)(bias + gN);
                    float v00 = fmaxf(acc[mt][j][0] + bv.x, 0.f);
                    float v01 = fmaxf(acc[mt][j][1] + bv.y, 0.f);
                    float v10 = fmaxf(acc[mt][j][2] + bv.x, 0.f);
                    float v11 = fmaxf(acc[mt][j][3] + bv.y, 0.f);
                    *(uint32_t*)&g_hhi[(size_t)gm * 256 + gN]       = pack_h2(v00, v01);
                    *(uint32_t*)&g_hhi[(size_t)(gm + 8) * 256 + gN] = pack_h2(v10, v11);
                } else if (gN < 128) {
                    *(float2*)(g_y + (size_t)gm * 128 + gN)       = make_float2(acc[mt][j][0], acc[mt][j][1]);
                    *(float2*)(g_y + (size_t)(gm + 8) * 128 + gN) = make_float2(acc[mt][j][2], acc[mt][j][3]);
                } else {
                    int nc = gN - 128;
                    float2 bv = *(const float2*)(bias + nc);
                    if (gm < NN)
                        *(float2*)(dout + (size_t)gm * 128 + nc) =
                            make_float2(acc[mt][j][0] + bv.x, acc[mt][j][1] + bv.y);
                    if (gm + 8 < NN)
                        *(float2*)(dout + (size_t)(gm + 8) * 128 + nc) =
                            make_float2(acc[mt][j][2] + bv.x, acc[mt][j][3] + bv.y);
                }
            }
        }
    }
}

// ---------------- launch ----------------
extern "C" void kernel_launch(void* const* d_in, const int* in_sizes, int n_in,
                              void* d_out, int out_size)
{
    const float* pol   = (const float*)d_in[0];
    const int*   sid   = (const int*)  d_in[1];
    const int*   ei    = (const int*)  d_in[2];
    const float* ew    = (const float*)d_in[3];
    const float* Wp    = (const float*)d_in[4];
    const float* bp    = (const float*)d_in[5];
    const float* semb  = (const float*)d_in[6];
    const float* tick  = (const float*)d_in[7];
    const float* W1rel = (const float*)d_in[8];
    const float* b1    = (const float*)d_in[9];
    const float* W1root= (const float*)d_in[10];
    const float* W2rel = (const float*)d_in[11];
    const float* b2    = (const float*)d_in[12];
    const float* W2root= (const float*)d_in[13];
    float* out = (float*)d_out;

    cudaFuncSetAttribute(gcn_gemm_mma<1>, cudaFuncAttributeMaxDynamicSharedMemorySize, SMTOT1);
    cudaFuncSetAttribute(gcn_gemm_mma<2>, cudaFuncAttributeMaxDynamicSharedMemorySize, SMTOT2);

    // 0) weight hi planes + zero g_cnt (fused)
    wconv_kernel<<<512, 256>>>(W1rel, W1root, W2rel, W2root);
    // 1) x build (split planes)
    build_x_kernel<<<(NN * 32 + 255) / 256, 256>>>(pol, sid, Wp, bp, semb, tick);
    // 2) CSR build
    hist_kernel<<<(E_EDGES + 255) / 256, 256>>>(ei);
    scan1_kernel<<<NB1, 256>>>();
    scan2_kernel<<<1, 512>>>();
    scan3_kernel<<<NB1, 256>>>();
    place_kernel<<<(E_EDGES + 255) / 256, 256>>>(ei, ew);
    // 3) gather1
    gather1_kernel<<<NN * 32 / 256, 256>>>();
    // 4) GEMM1 (2 products)
    gcn_gemm_mma<1><<<4 * NSLOT, 256, SMTOT1>>>(b1, nullptr);
    // 5) GEMM2 (1 product)
    gcn_gemm_mma<2><<<4 * NSLOT, 256, SMTOT2>>>(b2, out);
    // 6) gather2
    gather2_kernel<<<NN * 32 / 256, 256>>>(out);
}

// round 11
// speedup vs baseline: 4.4246x; 1.2316x over previous
#include <cuda_runtime.h>
#include <cuda_fp16.h>
#include <cstdint>

#define N_POL   100000
#define N_TICK  20000
#define NN      (N_POL + N_TICK)   // 120000
#define NPAD    120064
#define NB1     469
#define E_EDGES 1000000
#define POL_FEAT 7
#define EMB     128
#define HID     256
#define OUTD    128

// ---------------- scratch (static device globals; no allocation) ----------------
// fp16 single planes
__device__ uint16_t g_xh[(size_t)NPAD * EMB];     // x fp16
__device__ uint16_t g_a1h[(size_t)NPAD * EMB];    // agg1 fp16
__device__ uint16_t g_hh[(size_t)NPAD * HID];     // h fp16
__device__ uint16_t g_yh[(size_t)NPAD * EMB];     // y = h@W2rel fp16
__device__ uint16_t g_w1h[256 * 256];             // [n][k] fp16
__device__ uint16_t g_w2h[256 * 256];
// CSR structures
__device__ int  g_cnt[NPAD];
__device__ int  g_off[NPAD];
__device__ int  g_cur[NPAD];
__device__ int  g_bsum[NB1];
__device__ int  g_boff[NB1];
__device__ int2 g_edge[E_EDGES];    // {src, weight_bits} sorted by dst

// ---------------- helpers ----------------
__device__ __forceinline__ uint32_t smem_u32(const void* p) {
    uint32_t a;
    asm("{ .reg .u64 t; cvta.to.shared.u64 t, %1; cvt.u32.u64 %0, t; }" : "=r"(a) : "l"(p));
    return a;
}
#define LDSM_X4(r0, r1, r2, r3, addr) \
    asm volatile("ldmatrix.sync.aligned.m8n8.x4.shared.b16 {%0,%1,%2,%3}, [%4];" \
        : "=r"(r0), "=r"(r1), "=r"(r2), "=r"(r3) : "r"(addr))
#define MMA_F16(c, a, b0, b1) \
    asm volatile("mma.sync.aligned.m16n8k16.row.col.f32.f16.f16.f32 " \
        "{%0,%1,%2,%3}, {%4,%5,%6,%7}, {%8,%9}, {%0,%1,%2,%3};" \
        : "+f"((c)[0]), "+f"((c)[1]), "+f"((c)[2]), "+f"((c)[3]) \
        : "r"((a)[0]), "r"((a)[1]), "r"((a)[2]), "r"((a)[3]), "r"(b0), "r"(b1))
#define CP16(dst, src) \
    asm volatile("cp.async.cg.shared.global [%0], [%1], 16;" :: "r"(dst), "l"(src))
#define CP_COMMIT() asm volatile("cp.async.commit_group;" ::: "memory")
template <int N> __device__ __forceinline__ void cp_wait() {
    asm volatile("cp.async.wait_group %0;" :: "n"(N) : "memory");
}
__device__ __forceinline__ uint32_t pack_h2(float a, float b) {
    __half2 t = __floats2half2_rn(a, b);
    return *reinterpret_cast<uint32_t*>(&t);
}
__device__ __forceinline__ uint2 pack_h4(float4 v) {
    return make_uint2(pack_h2(v.x, v.y), pack_h2(v.z, v.w));
}
__device__ __forceinline__ float4 unpack_h4(uint2 p) {
    float2 a = __half22float2(*reinterpret_cast<__half2*>(&p.x));
    float2 b = __half22float2(*reinterpret_cast<__half2*>(&p.y));
    return make_float4(a.x, a.y, b.x, b.y);
}

// ---------------- weight conversion (fp16) + zero g_cnt ----------------
__global__ __launch_bounds__(256)
void wconv_kernel(const float* __restrict__ W1rel, const float* __restrict__ W1root,
                  const float* __restrict__ W2rel, const float* __restrict__ W2root)
{
    int idx = blockIdx.x * 256 + threadIdx.x;
    if (idx < NPAD / 4) ((int4*)g_cnt)[idx] = make_int4(0, 0, 0, 0);
    int which = idx >> 16;
    int e = idx & 65535;
    int n = e >> 8, k = e & 255;
    float v;
    if (which == 0) v = (k < 128) ? W1rel[k * 256 + n] : W1root[(k - 128) * 256 + n];
    else            v = (n < 128) ? W2rel[k * 128 + n] : W2root[k * 128 + (n - 128)];
    __half bh = __float2half(v);
    uint16_t h = *reinterpret_cast<uint16_t*>(&bh);
    if (which == 0) g_w1h[e] = h;
    else            g_w2h[e] = h;
}

// ---------------- CSR build kernels ----------------
__global__ __launch_bounds__(256)
void hist_kernel(const int* __restrict__ ei)
{
    int e = blockIdx.x * 256 + threadIdx.x;
    if (e < E_EDGES) atomicAdd(&g_cnt[ei[E_EDGES + e]], 1);
}

__global__ __launch_bounds__(256)
void scan1_kernel()
{
    __shared__ int s[256];
    int tid = threadIdx.x;
    int idx = blockIdx.x * 256 + tid;
    int v = g_cnt[idx];
    s[tid] = v;
    __syncthreads();
    #pragma unroll
    for (int d = 1; d < 256; d <<= 1) {
        int t = (tid >= d) ? s[tid - d] : 0;
        __syncthreads();
        s[tid] += t;
        __syncthreads();
    }
    g_off[idx] = s[tid] - v;
    if (tid == 255) g_bsum[blockIdx.x] = s[255];
}

__global__ __launch_bounds__(512)
void scan2_kernel()
{
    __shared__ int s[512];
    int tid = threadIdx.x;
    int v = (tid < NB1) ? g_bsum[tid] : 0;
    s[tid] = v;
    __syncthreads();
    #pragma unroll
    for (int d = 1; d < 512; d <<= 1) {
        int t = (tid >= d) ? s[tid - d] : 0;
        __syncthreads();
        s[tid] += t;
        __syncthreads();
    }
    if (tid < NB1) g_boff[tid] = s[tid] - v;
}

__global__ __launch_bounds__(256)
void scan3_kernel()
{
    int idx = blockIdx.x * 256 + threadIdx.x;
    int o = g_off[idx] + g_boff[blockIdx.x];
    g_off[idx] = o;
    g_cur[idx] = o;
}

__global__ __launch_bounds__(256)
void place_kernel(const int* __restrict__ ei, const float* __restrict__ ew)
{
    int e = blockIdx.x * 256 + threadIdx.x;
    if (e >= E_EDGES) return;
    int s = ei[e];
    int d = ei[E_EDGES + e];
    float w = ew[e];
    int pos = atomicAdd(&g_cur[d], 1);
    g_edge[pos] = make_int2(s, __float_as_int(w));
}

// ---------------- build x fp16 ----------------
__global__ __launch_bounds__(256)
void build_x_kernel(const float* __restrict__ pol, const int* __restrict__ sid,
                    const float* __restrict__ Wp, const float* __restrict__ bp,
                    const float* __restrict__ semb, const float* __restrict__ tick)
{
    int t = blockIdx.x * blockDim.x + threadIdx.x;
    int node = t >> 5;
    int c4 = (t & 31) * 4;
    if (node >= NN) return;

    float4 r;
    if (node < N_POL) {
        float4 acc = *(const float4*)(bp + c4);
        #pragma unroll
        for (int k = 0; k < POL_FEAT; k++) {
            float f = __ldg(pol + node * POL_FEAT + k);
            float4 w = *(const float4*)(Wp + k * EMB + c4);
            acc.x += f * w.x; acc.y += f * w.y; acc.z += f * w.z; acc.w += f * w.w;
        }
        int s = sid[node];
        float4 se = *(const float4*)(semb + (size_t)s * EMB + c4);
        r.x = fmaxf(acc.x, 0.f) + se.x;
        r.y = fmaxf(acc.y, 0.f) + se.y;
        r.z = fmaxf(acc.z, 0.f) + se.z;
        r.w = fmaxf(acc.w, 0.f) + se.w;
    } else {
        r = *(const float4*)(tick + (size_t)(node - N_POL) * EMB + c4);
    }
    *(uint2*)&g_xh[(size_t)node * EMB + c4] = pack_h4(r);
}

// ---------------- gather1: a1 = fp16( sum_e w * x[src] ) ----------------
__global__ __launch_bounds__(256)
void gather1_kernel()
{
    int t = blockIdx.x * blockDim.x + threadIdx.x;
    int node = t >> 5;
    int c4 = (t & 31) * 4;
    if (node >= NN) return;

    int cnt = __ldg(&g_cnt[node]);
    int off = __ldg(&g_off[node]);

    float4 acc = make_float4(0.f, 0.f, 0.f, 0.f);
    int i = 0;
    for (; i + 1 < cnt; i += 2) {
        int2 e0 = __ldg(&g_edge[off + i]);
        int2 e1 = __ldg(&g_edge[off + i + 1]);
        float4 v0 = unpack_h4(*(const uint2*)&g_xh[(size_t)e0.x * EMB + c4]);
        float4 v1 = unpack_h4(*(const uint2*)&g_xh[(size_t)e1.x * EMB + c4]);
        float w0 = __int_as_float(e0.y);
        float w1 = __int_as_float(e1.y);
        acc.x += w0 * v0.x + w1 * v1.x;
        acc.y += w0 * v0.y + w1 * v1.y;
        acc.z += w0 * v0.z + w1 * v1.z;
        acc.w += w0 * v0.w + w1 * v1.w;
    }
    if (i < cnt) {
        int2 e0 = __ldg(&g_edge[off + i]);
        float4 v0 = unpack_h4(*(const uint2*)&g_xh[(size_t)e0.x * EMB + c4]);
        float w0 = __int_as_float(e0.y);
        acc.x += w0 * v0.x; acc.y += w0 * v0.y;
        acc.z += w0 * v0.z; acc.w += w0 * v0.w;
    }

    *(uint2*)&g_a1h[(size_t)node * EMB + c4] = pack_h4(acc);
}

// ---------------- gather2: out += sum_e w * y[src]  (y fp16) ----------------
__global__ __launch_bounds__(256)
void gather2_kernel(float* __restrict__ out)
{
    int t = blockIdx.x * blockDim.x + threadIdx.x;
    int node = t >> 5;
    int c4 = (t & 31) * 4;
    if (node >= NN) return;

    int cnt = __ldg(&g_cnt[node]);
    if (cnt == 0) return;
    int off = __ldg(&g_off[node]);

    float4 acc = make_float4(0.f, 0.f, 0.f, 0.f);
    int i = 0;
    for (; i + 1 < cnt; i += 2) {
        int2 e0 = __ldg(&g_edge[off + i]);
        int2 e1 = __ldg(&g_edge[off + i + 1]);
        float4 v0 = unpack_h4(*(const uint2*)&g_yh[(size_t)e0.x * EMB + c4]);
        float4 v1 = unpack_h4(*(const uint2*)&g_yh[(size_t)e1.x * EMB + c4]);
        float w0 = __int_as_float(e0.y);
        float w1 = __int_as_float(e1.y);
        acc.x += w0 * v0.x + w1 * v1.x;
        acc.y += w0 * v0.y + w1 * v1.y;
        acc.z += w0 * v0.z + w1 * v1.z;
        acc.w += w0 * v0.w + w1 * v1.w;
    }
    if (i < cnt) {
        int2 e0 = __ldg(&g_edge[off + i]);
        float4 v0 = unpack_h4(*(const uint2*)&g_yh[(size_t)e0.x * EMB + c4]);
        float w0 = __int_as_float(e0.y);
        acc.x += w0 * v0.x; acc.y += w0 * v0.y;
        acc.z += w0 * v0.z; acc.w += w0 * v0.w;
    }

    float* o = out + (size_t)node * EMB + c4;
    float4 cur = *(float4*)o;
    cur.x += acc.x; cur.y += acc.y; cur.z += acc.z; cur.w += acc.w;
    *(float4*)o = cur;
}

// =========== persistent-B HMMA fp16 GEMM (single product) ===========
// MODE 1: A = [a1|x] fp16, writes g_hh = fp16(relu(acc + b1))
// MODE 2: A = h fp16, writes y fp16 | out f32 (+b2)
#define A_KSTR  40
#define A_PLANE (128 * A_KSTR * 2)        // 10240
#define B_KSTR  264
#define B_PLANE (64 * B_KSTR * 2)         // 33792
#define SM_A    (B_PLANE)
#define SMTOT   (SM_A + 2 * A_PLANE)      // 54272
#define NSLOT   111                       // 444 CTAs / 4 quarters (3 per SM)

template <int MODE>
__global__ __launch_bounds__(256, 3)
void gcn_gemm_mma(const float* __restrict__ bias, float* __restrict__ dout)
{
    extern __shared__ char smem[];
    const uint32_t sb = smem_u32(smem);

    const int tid  = threadIdx.x;
    const int lane = tid & 31;
    const int wid  = tid >> 5;
    const int wm   = wid >> 1;
    const int wn   = wid & 1;
    const int q    = blockIdx.x & 3;
    const int slot = blockIdx.x >> 2;

    const uint16_t* wh = (MODE == 1) ? g_w1h : g_w2h;

    // ---- load B quarter once: [64 n][256 k]
    #pragma unroll
    for (int i = 0; i < 8; i++) {
        int c = i * 256 + tid;
        int row = c >> 5;
        int col = c & 31;
        const uint16_t* src = wh + (size_t)(q * 64 + row) * 256 + col * 8;
        uint32_t dst = sb + (uint32_t)(row * B_KSTR + col * 8) * 2;
        CP16(dst, src);
    }
    CP_COMMIT();
    cp_wait<0>();
    __syncthreads();

    auto issue = [&](int m0, int kc, int st) {
        const uint16_t* ah;
        int astr, kb;
        if (MODE == 1) {
            ah = (kc < 4) ? g_a1h : g_xh;
            astr = 128; kb = (kc & 3) * 32;
        } else {
            ah = g_hh; astr = 256; kb = kc * 32;
        }
        uint32_t base = sb + SM_A + st * A_PLANE;
        #pragma unroll
        for (int i = 0; i < 2; i++) {
            int c = i * 256 + tid;          // 0..511
            int row = c >> 2;               // 0..127
            int col = c & 3;
            const uint16_t* src = ah + (size_t)(m0 + row) * astr + kb + col * 8;
            uint32_t dst = base + (uint32_t)(row * A_KSTR + col * 8) * 2;
            CP16(dst, src);
        }
        CP_COMMIT();
    };

    const int rA = (lane & 7) + ((lane >> 3) & 1) * 8;
    const int kA = (lane >> 4) * 8;
    const int rB = (lane & 7) + ((lane >> 4) & 1) * 8;
    const int kB = ((lane >> 3) & 1) * 8;
    const int rr = lane >> 2;
    const int cc = (lane & 3) * 2;

    for (int t = slot; t < NPAD / 128; t += NSLOT) {
        const int m0 = t * 128;

        float acc[2][4][4];
        #pragma unroll
        for (int i = 0; i < 2; i++)
            #pragma unroll
            for (int j = 0; j < 4; j++)
                #pragma unroll
                for (int p = 0; p < 4; p++) acc[i][j][p] = 0.f;

        issue(m0, 0, 0);

        for (int kc = 0; kc < 8; kc++) {
            cp_wait<0>();
            __syncthreads();
            if (kc + 1 < 8) issue(m0, kc + 1, (kc + 1) & 1);

            uint32_t uA = sb + SM_A + (kc & 1) * A_PLANE;

            #pragma unroll
            for (int ks = 0; ks < 2; ks++) {
                uint32_t ah[2][4];
                #pragma unroll
                for (int mt = 0; mt < 2; mt++) {
                    uint32_t off = ((uint32_t)((wm * 32 + mt * 16 + rA) * A_KSTR + ks * 16 + kA)) * 2;
                    LDSM_X4(ah[mt][0], ah[mt][1], ah[mt][2], ah[mt][3], uA + off);
                }
                #pragma unroll
                for (int np = 0; np < 2; np++) {
                    uint32_t boff = ((uint32_t)((wn * 32 + np * 16 + rB) * B_KSTR + kc * 32 + ks * 16 + kB)) * 2;
                    uint32_t bh[4];
                    LDSM_X4(bh[0], bh[1], bh[2], bh[3], sb + boff);
                    #pragma unroll
                    for (int mt = 0; mt < 2; mt++) {
                        MMA_F16(acc[mt][np * 2 + 0], ah[mt], bh[0], bh[1]);
                        MMA_F16(acc[mt][np * 2 + 1], ah[mt], bh[2], bh[3]);
                    }
                }
            }
            __syncthreads();
        }

        #pragma unroll
        for (int mt = 0; mt < 2; mt++) {
            #pragma unroll
            for (int j = 0; j < 4; j++) {
                int gm = m0 + wm * 32 + mt * 16 + rr;
                int gN = q * 64 + wn * 32 + j * 8 + cc;
                if (MODE == 1) {
                    float2 bv = *(const float2*)(bias + gN);
                    float v00 = fmaxf(acc[mt][j][0] + bv.x, 0.f);
                    float v01 = fmaxf(acc[mt][j][1] + bv.y, 0.f);
                    float v10 = fmaxf(acc[mt][j][2] + bv.x, 0.f);
                    float v11 = fmaxf(acc[mt][j][3] + bv.y, 0.f);
                    *(uint32_t*)&g_hh[(size_t)gm * 256 + gN]       = pack_h2(v00, v01);
                    *(uint32_t*)&g_hh[(size_t)(gm + 8) * 256 + gN] = pack_h2(v10, v11);
                } else if (gN < 128) {
                    *(uint32_t*)&g_yh[(size_t)gm * 128 + gN]       = pack_h2(acc[mt][j][0], acc[mt][j][1]);
                    *(uint32_t*)&g_yh[(size_t)(gm + 8) * 128 + gN] = pack_h2(acc[mt][j][2], acc[mt][j][3]);
                } else {
                    int nc = gN - 128;
                    float2 bv = *(const float2*)(bias + nc);
                    if (gm < NN)
                        *(float2*)(dout + (size_t)gm * 128 + nc) =
                            make_float2(acc[mt][j][0] + bv.x, acc[mt][j][1] + bv.y);
                    if (gm + 8 < NN)
                        *(float2*)(dout + (size_t)(gm + 8) * 128 + nc) =
                            make_float2(acc[mt][j][2] + bv.x, acc[mt][j][3] + bv.y);
                }
            }
        }
    }
}

// ---------------- launch ----------------
extern "C" void kernel_launch(void* const* d_in, const int* in_sizes, int n_in,
                              void* d_out, int out_size)
{
    const float* pol   = (const float*)d_in[0];
    const int*   sid   = (const int*)  d_in[1];
    const int*   ei    = (const int*)  d_in[2];
    const float* ew    = (const float*)d_in[3];
    const float* Wp    = (const float*)d_in[4];
    const float* bp    = (const float*)d_in[5];
    const float* semb  = (const float*)d_in[6];
    const float* tick  = (const float*)d_in[7];
    const float* W1rel = (const float*)d_in[8];
    const float* b1    = (const float*)d_in[9];
    const float* W1root= (const float*)d_in[10];
    const float* W2rel = (const float*)d_in[11];
    const float* b2    = (const float*)d_in[12];
    const float* W2root= (const float*)d_in[13];
    float* out = (float*)d_out;

    cudaFuncSetAttribute(gcn_gemm_mma<1>, cudaFuncAttributeMaxDynamicSharedMemorySize, SMTOT);
    cudaFuncSetAttribute(gcn_gemm_mma<2>, cudaFuncAttributeMaxDynamicSharedMemorySize, SMTOT);

    // 0) weight fp16 + zero g_cnt (fused)
    wconv_kernel<<<512, 256>>>(W1rel, W1root, W2rel, W2root);
    // 1) x build fp16
    build_x_kernel<<<(NN * 32 + 255) / 256, 256>>>(pol, sid, Wp, bp, semb, tick);
    // 2) CSR build
    hist_kernel<<<(E_EDGES + 255) / 256, 256>>>(ei);
    scan1_kernel<<<NB1, 256>>>();
    scan2_kernel<<<1, 512>>>();
    scan3_kernel<<<NB1, 256>>>();
    place_kernel<<<(E_EDGES + 255) / 256, 256>>>(ei, ew);
    // 3) gather1
    gather1_kernel<<<NN * 32 / 256, 256>>>();
    // 4) GEMM1
    gcn_gemm_mma<1><<<4 * NSLOT, 256, SMTOT>>>(b1, nullptr);
    // 5) GEMM2
    gcn_gemm_mma<2><<<4 * NSLOT, 256, SMTOT>>>(b2, out);
    // 6) gather2
    gather2_kernel<<<NN * 32 / 256, 256>>>(out);
}

// round 12
// speedup vs baseline: 4.5892x; 1.0372x over previous
#include <cuda_runtime.h>
#include <cuda_fp16.h>
#include <cstdint>

#define N_POL   100000
#define N_TICK  20000
#define NN      (N_POL + N_TICK)   // 120000
#define NPAD    120064
#define NB1     469
#define E_EDGES 1000000
#define POL_FEAT 7
#define EMB     128
#define HID     256
#define OUTD    128

// ---------------- scratch (static device globals; no allocation) ----------------
__device__ uint16_t g_xh[(size_t)NPAD * EMB];     // x fp16
__device__ uint16_t g_a1h[(size_t)NPAD * EMB];    // agg1 fp16
__device__ uint16_t g_hh[(size_t)NPAD * HID];     // h fp16
__device__ uint16_t g_yh[(size_t)NPAD * EMB];     // y = h@W2rel fp16
__device__ uint16_t g_w1h[256 * 256];             // [n][k] fp16
__device__ uint16_t g_w2h[256 * 256];
// CSR structures
__device__ int  g_cnt[NPAD];
__device__ int  g_off[NPAD];
__device__ int  g_cur[NPAD];
__device__ int  g_bsum[NB1];
__device__ int2 g_edge[E_EDGES];    // {src, weight_bits} sorted by dst

// ---------------- helpers ----------------
__device__ __forceinline__ uint32_t smem_u32(const void* p) {
    uint32_t a;
    asm("{ .reg .u64 t; cvta.to.shared.u64 t, %1; cvt.u32.u64 %0, t; }" : "=r"(a) : "l"(p));
    return a;
}
#define LDSM_X4(r0, r1, r2, r3, addr) \
    asm volatile("ldmatrix.sync.aligned.m8n8.x4.shared.b16 {%0,%1,%2,%3}, [%4];" \
        : "=r"(r0), "=r"(r1), "=r"(r2), "=r"(r3) : "r"(addr))
#define MMA_F16(c, a, b0, b1) \
    asm volatile("mma.sync.aligned.m16n8k16.row.col.f32.f16.f16.f32 " \
        "{%0,%1,%2,%3}, {%4,%5,%6,%7}, {%8,%9}, {%0,%1,%2,%3};" \
        : "+f"((c)[0]), "+f"((c)[1]), "+f"((c)[2]), "+f"((c)[3]) \
        : "r"((a)[0]), "r"((a)[1]), "r"((a)[2]), "r"((a)[3]), "r"(b0), "r"(b1))
#define CP16(dst, src) \
    asm volatile("cp.async.cg.shared.global [%0], [%1], 16;" :: "r"(dst), "l"(src))
#define CP_COMMIT() asm volatile("cp.async.commit_group;" ::: "memory")
template <int N> __device__ __forceinline__ void cp_wait() {
    asm volatile("cp.async.wait_group %0;" :: "n"(N) : "memory");
}
__device__ __forceinline__ uint32_t pack_h2(float a, float b) {
    __half2 t = __floats2half2_rn(a, b);
    return *reinterpret_cast<uint32_t*>(&t);
}
__device__ __forceinline__ uint2 pack_h4(float4 v) {
    return make_uint2(pack_h2(v.x, v.y), pack_h2(v.z, v.w));
}
__device__ __forceinline__ float4 unpack_h4(uint2 p) {
    float2 a = __half22float2(*reinterpret_cast<__half2*>(&p.x));
    float2 b = __half22float2(*reinterpret_cast<__half2*>(&p.y));
    return make_float4(a.x, a.y, b.x, b.y);
}

// ---------------- fused prep: build_x fp16 | weight fp16 + zero g_cnt ----------------
#define BX_BLOCKS 15000   // NN*32/256
__global__ __launch_bounds__(256)
void prep_kernel(const float* __restrict__ pol, const int* __restrict__ sid,
                 const float* __restrict__ Wp, const float* __restrict__ bp,
                 const float* __restrict__ semb, const float* __restrict__ tick,
                 const float* __restrict__ W1rel, const float* __restrict__ W1root,
                 const float* __restrict__ W2rel, const float* __restrict__ W2root)
{
    if (blockIdx.x < BX_BLOCKS) {
        int t = blockIdx.x * 256 + threadIdx.x;
        int node = t >> 5;
        int c4 = (t & 31) * 4;
        if (node >= NN) return;
        float4 r;
        if (node < N_POL) {
            float4 acc = *(const float4*)(bp + c4);
            #pragma unroll
            for (int k = 0; k < POL_FEAT; k++) {
                float f = __ldg(pol + node * POL_FEAT + k);
                float4 w = *(const float4*)(Wp + k * EMB + c4);
                acc.x += f * w.x; acc.y += f * w.y; acc.z += f * w.z; acc.w += f * w.w;
            }
            int s = sid[node];
            float4 se = *(const float4*)(semb + (size_t)s * EMB + c4);
            r.x = fmaxf(acc.x, 0.f) + se.x;
            r.y = fmaxf(acc.y, 0.f) + se.y;
            r.z = fmaxf(acc.z, 0.f) + se.z;
            r.w = fmaxf(acc.w, 0.f) + se.w;
        } else {
            r = *(const float4*)(tick + (size_t)(node - N_POL) * EMB + c4);
        }
        *(uint2*)&g_xh[(size_t)node * EMB + c4] = pack_h4(r);
    } else {
        int idx = (blockIdx.x - BX_BLOCKS) * 256 + threadIdx.x;   // 0..131071
        if (idx < NPAD / 4) ((int4*)g_cnt)[idx] = make_int4(0, 0, 0, 0);
        int which = idx >> 16;
        int e = idx & 65535;
        int n = e >> 8, k = e & 255;
        float v;
        if (which == 0) v = (k < 128) ? W1rel[k * 256 + n] : W1root[(k - 128) * 256 + n];
        else            v = (n < 128) ? W2rel[k * 128 + n] : W2root[k * 128 + (n - 128)];
        __half bh = __float2half(v);
        uint16_t h = *reinterpret_cast<uint16_t*>(&bh);
        if (which == 0) g_w1h[e] = h;
        else            g_w2h[e] = h;
    }
}

// ---------------- CSR build kernels ----------------
__global__ __launch_bounds__(256)
void hist_kernel(const int* __restrict__ ei)
{
    int e = blockIdx.x * 256 + threadIdx.x;
    if (e < E_EDGES) atomicAdd(&g_cnt[ei[E_EDGES + e]], 1);
}

__global__ __launch_bounds__(256)
void scan1_kernel()
{
    __shared__ int s[256];
    int tid = threadIdx.x;
    int idx = blockIdx.x * 256 + tid;
    int v = g_cnt[idx];
    s[tid] = v;
    __syncthreads();
    #pragma unroll
    for (int d = 1; d < 256; d <<= 1) {
        int t = (tid >= d) ? s[tid - d] : 0;
        __syncthreads();
        s[tid] += t;
        __syncthreads();
    }
    g_off[idx] = s[tid] - v;
    if (tid == 255) g_bsum[blockIdx.x] = s[255];
}

// fused scan2+scan3: each block reduces bsum[0..bid) and applies base
__global__ __launch_bounds__(256)
void scan23_kernel()
{
    __shared__ int sh[256];
    int tid = threadIdx.x;
    int bid = blockIdx.x;
    int part = 0;
    for (int j = tid; j < bid; j += 256) part += g_bsum[j];
    sh[tid] = part;
    __syncthreads();
    #pragma unroll
    for (int d = 128; d > 0; d >>= 1) {
        if (tid < d) sh[tid] += sh[tid + d];
        __syncthreads();
    }
    int base = sh[0];
    int idx = bid * 256 + tid;
    int o = g_off[idx] + base;
    g_off[idx] = o;
    g_cur[idx] = o;
}

__global__ __launch_bounds__(256)
void place_kernel(const int* __restrict__ ei, const float* __restrict__ ew)
{
    int e = blockIdx.x * 256 + threadIdx.x;
    if (e >= E_EDGES) return;
    int s = ei[e];
    int d = ei[E_EDGES + e];
    float w = ew[e];
    int pos = atomicAdd(&g_cur[d], 1);
    g_edge[pos] = make_int2(s, __float_as_int(w));
}

// ---------------- gather1: a1 = fp16( sum_e w * x[src] ) ----------------
__global__ __launch_bounds__(256)
void gather1_kernel()
{
    int t = blockIdx.x * blockDim.x + threadIdx.x;
    int node = t >> 5;
    int c4 = (t & 31) * 4;
    if (node >= NN) return;

    int cnt = __ldg(&g_cnt[node]);
    int off = __ldg(&g_off[node]);

    float4 acc = make_float4(0.f, 0.f, 0.f, 0.f);
    int i = 0;
    for (; i + 1 < cnt; i += 2) {
        int2 e0 = __ldg(&g_edge[off + i]);
        int2 e1 = __ldg(&g_edge[off + i + 1]);
        float4 v0 = unpack_h4(*(const uint2*)&g_xh[(size_t)e0.x * EMB + c4]);
        float4 v1 = unpack_h4(*(const uint2*)&g_xh[(size_t)e1.x * EMB + c4]);
        float w0 = __int_as_float(e0.y);
        float w1 = __int_as_float(e1.y);
        acc.x += w0 * v0.x + w1 * v1.x;
        acc.y += w0 * v0.y + w1 * v1.y;
        acc.z += w0 * v0.z + w1 * v1.z;
        acc.w += w0 * v0.w + w1 * v1.w;
    }
    if (i < cnt) {
        int2 e0 = __ldg(&g_edge[off + i]);
        float4 v0 = unpack_h4(*(const uint2*)&g_xh[(size_t)e0.x * EMB + c4]);
        float w0 = __int_as_float(e0.y);
        acc.x += w0 * v0.x; acc.y += w0 * v0.y;
        acc.z += w0 * v0.z; acc.w += w0 * v0.w;
    }

    *(uint2*)&g_a1h[(size_t)node * EMB + c4] = pack_h4(acc);
}

// ---------------- gather2: out += sum_e w * y[src]  (y fp16) ----------------
__global__ __launch_bounds__(256)
void gather2_kernel(float* __restrict__ out)
{
    int t = blockIdx.x * blockDim.x + threadIdx.x;
    int node = t >> 5;
    int c4 = (t & 31) * 4;
    if (node >= NN) return;

    int cnt = __ldg(&g_cnt[node]);
    if (cnt == 0) return;
    int off = __ldg(&g_off[node]);

    float4 acc = make_float4(0.f, 0.f, 0.f, 0.f);
    int i = 0;
    for (; i + 1 < cnt; i += 2) {
        int2 e0 = __ldg(&g_edge[off + i]);
        int2 e1 = __ldg(&g_edge[off + i + 1]);
        float4 v0 = unpack_h4(*(const uint2*)&g_yh[(size_t)e0.x * EMB + c4]);
        float4 v1 = unpack_h4(*(const uint2*)&g_yh[(size_t)e1.x * EMB + c4]);
        float w0 = __int_as_float(e0.y);
        float w1 = __int_as_float(e1.y);
        acc.x += w0 * v0.x + w1 * v1.x;
        acc.y += w0 * v0.y + w1 * v1.y;
        acc.z += w0 * v0.z + w1 * v1.z;
        acc.w += w0 * v0.w + w1 * v1.w;
    }
    if (i < cnt) {
        int2 e0 = __ldg(&g_edge[off + i]);
        float4 v0 = unpack_h4(*(const uint2*)&g_yh[(size_t)e0.x * EMB + c4]);
        float w0 = __int_as_float(e0.y);
        acc.x += w0 * v0.x; acc.y += w0 * v0.y;
        acc.z += w0 * v0.z; acc.w += w0 * v0.w;
    }

    float* o = out + (size_t)node * EMB + c4;
    float4 cur = *(float4*)o;
    cur.x += acc.x; cur.y += acc.y; cur.z += acc.z; cur.w += acc.w;
    *(float4*)o = cur;
}

// =========== persistent-B HMMA fp16 GEMM, BK=64 (4 chunks) ===========
// MODE 1: A = [a1|x] fp16, writes g_hh = fp16(relu(acc + b1))
// MODE 2: A = h fp16, writes y fp16 | out f32 (+b2)
#define A_KSTR  72                        // 64 + 8 pad fp16
#define A_PLANE (128 * A_KSTR * 2)        // 18432
#define B_KSTR  264
#define B_PLANE (64 * B_KSTR * 2)         // 33792
#define SM_A    (B_PLANE)
#define SMTOT   (SM_A + 2 * A_PLANE)      // 70656
#define NSLOT   111                       // 444 CTAs / 4 quarters (3 per SM)

template <int MODE>
__global__ __launch_bounds__(256, 3)
void gcn_gemm_mma(const float* __restrict__ bias, float* __restrict__ dout)
{
    extern __shared__ char smem[];
    const uint32_t sb = smem_u32(smem);

    const int tid  = threadIdx.x;
    const int lane = tid & 31;
    const int wid  = tid >> 5;
    const int wm   = wid >> 1;
    const int wn   = wid & 1;
    const int q    = blockIdx.x & 3;
    const int slot = blockIdx.x >> 2;

    const uint16_t* wh = (MODE == 1) ? g_w1h : g_w2h;

    // ---- load B quarter once: [64 n][256 k]
    #pragma unroll
    for (int i = 0; i < 8; i++) {
        int c = i * 256 + tid;
        int row = c >> 5;
        int col = c & 31;
        const uint16_t* src = wh + (size_t)(q * 64 + row) * 256 + col * 8;
        uint32_t dst = sb + (uint32_t)(row * B_KSTR + col * 8) * 2;
        CP16(dst, src);
    }
    CP_COMMIT();
    cp_wait<0>();
    __syncthreads();

    // A-chunk issue: chunk kc (64 k) of m-tile m0 into stage st
    auto issue = [&](int m0, int kc, int st) {
        const uint16_t* ah;
        int astr, kb;
        if (MODE == 1) {
            ah = (kc < 2) ? g_a1h : g_xh;
            astr = 128; kb = (kc & 1) * 64;
        } else {
            ah = g_hh; astr = 256; kb = kc * 64;
        }
        uint32_t base = sb + SM_A + st * A_PLANE;
        #pragma unroll
        for (int i = 0; i < 4; i++) {
            int c = i * 256 + tid;          // 0..1023
            int row = c >> 3;               // 0..127
            int col = c & 7;                // 16B chunk (8 fp16)
            const uint16_t* src = ah + (size_t)(m0 + row) * astr + kb + col * 8;
            uint32_t dst = base + (uint32_t)(row * A_KSTR + col * 8) * 2;
            CP16(dst, src);
        }
        CP_COMMIT();
    };

    const int rA = (lane & 7) + ((lane >> 3) & 1) * 8;
    const int kA = (lane >> 4) * 8;
    const int rB = (lane & 7) + ((lane >> 4) & 1) * 8;
    const int kB = ((lane >> 3) & 1) * 8;
    const int rr = lane >> 2;
    const int cc = (lane & 3) * 2;

    for (int t = slot; t < NPAD / 128; t += NSLOT) {
        const int m0 = t * 128;

        float acc[2][4][4];
        #pragma unroll
        for (int i = 0; i < 2; i++)
            #pragma unroll
            for (int j = 0; j < 4; j++)
                #pragma unroll
                for (int p = 0; p < 4; p++) acc[i][j][p] = 0.f;

        issue(m0, 0, 0);

        for (int kc = 0; kc < 4; kc++) {
            cp_wait<0>();              // stage kc data landed
            __syncthreads();           // publish + protect other stage before reuse
            if (kc + 1 < 4) issue(m0, kc + 1, (kc + 1) & 1);

            uint32_t uA = sb + SM_A + (kc & 1) * A_PLANE;

            #pragma unroll
            for (int ks = 0; ks < 4; ks++) {
                uint32_t ah[2][4];
                #pragma unroll
                for (int mt = 0; mt < 2; mt++) {
                    uint32_t off = ((uint32_t)((wm * 32 + mt * 16 + rA) * A_KSTR + ks * 16 + kA)) * 2;
                    LDSM_X4(ah[mt][0], ah[mt][1], ah[mt][2], ah[mt][3], uA + off);
                }
                #pragma unroll
                for (int np = 0; np < 2; np++) {
                    uint32_t boff = ((uint32_t)((wn * 32 + np * 16 + rB) * B_KSTR + kc * 64 + ks * 16 + kB)) * 2;
                    uint32_t bh[4];
                    LDSM_X4(bh[0], bh[1], bh[2], bh[3], sb + boff);
                    #pragma unroll
                    for (int mt = 0; mt < 2; mt++) {
                        MMA_F16(acc[mt][np * 2 + 0], ah[mt], bh[0], bh[1]);
                        MMA_F16(acc[mt][np * 2 + 1], ah[mt], bh[2], bh[3]);
                    }
                }
            }
            __syncthreads();           // reads of stage kc done before reuse at kc+2
        }

        #pragma unroll
        for (int mt = 0; mt < 2; mt++) {
            #pragma unroll
            for (int j = 0; j < 4; j++) {
                int gm = m0 + wm * 32 + mt * 16 + rr;
                int gN = q * 64 + wn * 32 + j * 8 + cc;
                if (MODE == 1) {
                    float2 bv = *(const float2*)(bias + gN);
                    float v00 = fmaxf(acc[mt][j][0] + bv.x, 0.f);
                    float v01 = fmaxf(acc[mt][j][1] + bv.y, 0.f);
                    float v10 = fmaxf(acc[mt][j][2] + bv.x, 0.f);
                    float v11 = fmaxf(acc[mt][j][3] + bv.y, 0.f);
                    *(uint32_t*)&g_hh[(size_t)gm * 256 + gN]       = pack_h2(v00, v01);
                    *(uint32_t*)&g_hh[(size_t)(gm + 8) * 256 + gN] = pack_h2(v10, v11);
                } else if (gN < 128) {
                    *(uint32_t*)&g_yh[(size_t)gm * 128 + gN]       = pack_h2(acc[mt][j][0], acc[mt][j][1]);
                    *(uint32_t*)&g_yh[(size_t)(gm + 8) * 128 + gN] = pack_h2(acc[mt][j][2], acc[mt][j][3]);
                } else {
                    int nc = gN - 128;
                    float2 bv = *(const float2*)(bias + nc);
                    if (gm < NN)
                        *(float2*)(dout + (size_t)gm * 128 + nc) =
                            make_float2(acc[mt][j][0] + bv.x, acc[mt][j][1] + bv.y);
                    if (gm + 8 < NN)
                        *(float2*)(dout + (size_t)(gm + 8) * 128 + nc) =
                            make_float2(acc[mt][j][2] + bv.x, acc[mt][j][3] + bv.y);
                }
            }
        }
    }
}

// ---------------- launch ----------------
extern "C" void kernel_launch(void* const* d_in, const int* in_sizes, int n_in,
                              void* d_out, int out_size)
{
    const float* pol   = (const float*)d_in[0];
    const int*   sid   = (const int*)  d_in[1];
    const int*   ei    = (const int*)  d_in[2];
    const float* ew    = (const float*)d_in[3];
    const float* Wp    = (const float*)d_in[4];
    const float* bp    = (const float*)d_in[5];
    const float* semb  = (const float*)d_in[6];
    const float* tick  = (const float*)d_in[7];
    const float* W1rel = (const float*)d_in[8];
    const float* b1    = (const float*)d_in[9];
    const float* W1root= (const float*)d_in[10];
    const float* W2rel = (const float*)d_in[11];
    const float* b2    = (const float*)d_in[12];
    const float* W2root= (const float*)d_in[13];
    float* out = (float*)d_out;

    cudaFuncSetAttribute(gcn_gemm_mma<1>, cudaFuncAttributeMaxDynamicSharedMemorySize, SMTOT);
    cudaFuncSetAttribute(gcn_gemm_mma<2>, cudaFuncAttributeMaxDynamicSharedMemorySize, SMTOT);

    // 0) fused prep: x fp16 | W fp16 + zero g_cnt
    prep_kernel<<<BX_BLOCKS + 512, 256>>>(pol, sid, Wp, bp, semb, tick,
                                          W1rel, W1root, W2rel, W2root);
    // 1) CSR build
    hist_kernel<<<(E_EDGES + 255) / 256, 256>>>(ei);
    scan1_kernel<<<NB1, 256>>>();
    scan23_kernel<<<NB1, 256>>>();
    place_kernel<<<(E_EDGES + 255) / 256, 256>>>(ei, ew);
    // 2) gather1
    gather1_kernel<<<NN * 32 / 256, 256>>>();
    // 3) GEMM1
    gcn_gemm_mma<1><<<4 * NSLOT, 256, SMTOT>>>(b1, nullptr);
    // 4) GEMM2
    gcn_gemm_mma<2><<<4 * NSLOT, 256, SMTOT>>>(b2, out);
    // 5) gather2
    gather2_kernel<<<NN * 32 / 256, 256>>>(out);
}